// round 5
// baseline (speedup 1.0000x reference)
#include <cuda_runtime.h>
#include <cuda_fp16.h>
#include <math.h>

#define H 128
#define G 50
#define NBINS 1024
#define CUTOFF_F 10.0f
#define NMAX 10000
#define EMAX 320000
#define PI_F 3.14159265358979323846f

__device__ __align__(16) float  g_h[NMAX * H];
__device__ __align__(16) __half g_xfh[NMAX * H];
__device__ __align__(16) float  g_agg[NMAX * H];
__device__ __align__(16) __half g_tabh[(NBINS + 2) * H];
__device__ __align__(16) __half2 g_tab2[NBINS * H];   // [b][f] = (W[b][f], W[b+1][f])
__device__ float g_acc[64];
__device__ int  g_rowptr[NMAX + 1];
__device__ int  g_cursor[NMAX];
__device__ __align__(16) int2 g_csr[EMAX];

__device__ __forceinline__ float sspf(float x) {
    return fmaxf(x, 0.f) + log1pf(expf(-fabsf(x))) - 0.69314718055994530942f;
}
__device__ __forceinline__ unsigned int h2_as_u32(__half2 h) {
    return *reinterpret_cast<unsigned int*>(&h);
}

// ---- f32x2 packed-FMA helpers ----
__device__ __forceinline__ void fma2(unsigned long long& d, unsigned long long a, unsigned long long b) {
    asm("fma.rn.f32x2 %0, %1, %2, %0;" : "+l"(d) : "l"(a), "l"(b));
}
__device__ __forceinline__ unsigned long long bcast2(float a) {
    unsigned long long r; asm("mov.b64 %0, {%1, %1};" : "=l"(r) : "f"(a)); return r;
}
__device__ __forceinline__ unsigned long long pack2(float a, float b) {
    unsigned long long r; asm("mov.b64 %0, {%1, %2};" : "=l"(r) : "f"(a), "f"(b)); return r;
}
__device__ __forceinline__ float2 unpack2(unsigned long long v) {
    float2 f; asm("mov.b64 {%0, %1}, %2;" : "=f"(f.x), "=f"(f.y) : "l"(v)); return f;
}

__global__ void embed_kernel(const int* __restrict__ x, const float* __restrict__ emb, int N) {
    int n = blockIdx.x;
    if (n < N) g_h[n * H + threadIdx.x] = emb[x[n] * H + threadIdx.x];
}

// ======================= CSR build =======================
__global__ void hist_kernel(const int* __restrict__ dst, int E) {
    int e = blockIdx.x * blockDim.x + threadIdx.x;
    if (e < E) atomicAdd(&g_rowptr[dst[e] + 1], 1);
}

__global__ void __launch_bounds__(1024) scan_kernel(int n) {
    __shared__ int sums[1024];
    int t = threadIdx.x;
    int C = (n + 1023) / 1024;
    int local[12];
    int base = t * C;
    int s = 0;
#pragma unroll
    for (int i = 0; i < 12; i++) {
        if (i >= C) break;
        int idx = base + i;
        int v = (idx < n) ? g_rowptr[idx] : 0;
        s += v; local[i] = s;
    }
    sums[t] = s;
    __syncthreads();
    for (int off = 1; off < 1024; off <<= 1) {
        int v = (t >= off) ? sums[t - off] : 0;
        __syncthreads();
        sums[t] += v;
        __syncthreads();
    }
    int prev = (t > 0) ? sums[t - 1] : 0;
#pragma unroll
    for (int i = 0; i < 12; i++) {
        if (i >= C) break;
        int idx = base + i;
        if (idx < n) g_rowptr[idx] = local[i] + prev;
    }
}

__global__ void scatter_kernel(const int* __restrict__ src, const int* __restrict__ dst,
                               const float* __restrict__ dist, int E) {
    int e = blockIdx.x * blockDim.x + threadIdx.x;
    if (e < E) {
        int p = atomicAdd(&g_cursor[dst[e]], 1);
        g_csr[p] = make_int2(src[e], __float_as_int(dist[e]));
    }
}

// ======================= Fused filter-table build =======================
__global__ void __launch_bounds__(128) table_fused(
    const float* __restrict__ w1, const float* __restrict__ b1,
    const float* __restrict__ w2, const float* __restrict__ b2)
{
    __shared__ float a_s[2][H];
    __shared__ float eas[2][G];
    int f = threadIdx.x;
    int b0 = blockIdx.x * 2;
    const float spacing = CUTOFF_F / (G - 1);
    const float coeff = -0.5f / (spacing * spacing);
    if (f < 2 * G) {
        int i = f / G, g = f - i * G;
        float d = (b0 + i) * (CUTOFF_F / NBINS);
        float dd = d - g * spacing;
        eas[i][g] = expf(coeff * dd * dd);
    }
    __syncthreads();
    float bv = b1[f];
    float a0 = bv, a1 = bv;
#pragma unroll
    for (int g = 0; g < G; g++) {
        float w = w1[g * H + f];
        a0 += eas[0][g] * w;
        a1 += eas[1][g] * w;
    }
    a_s[0][f] = sspf(a0);
    a_s[1][f] = sspf(a1);
    __syncthreads();
    unsigned long long accA = 0ull, accB = 0ull;
#pragma unroll 8
    for (int j = 0; j < H; j += 2) {
        float wA = w2[j * H + f];
        float wB = w2[(j + 1) * H + f];
        fma2(accA, pack2(a_s[0][j], a_s[1][j]), bcast2(wA));
        fma2(accB, pack2(a_s[0][j + 1], a_s[1][j + 1]), bcast2(wB));
    }
    float2 vA = unpack2(accA), vB = unpack2(accB);
    float b2v = b2[f];
    float v0 = vA.x + vB.x + b2v;
    float v1 = vA.y + vB.y + b2v;
    if (b0 <= NBINS) {
        float d = b0 * (CUTOFF_F / NBINS);
        g_tabh[b0 * H + f] = __float2half(v0 * 0.5f * (cosf(d * (PI_F / CUTOFF_F)) + 1.f));
    }
    if (b0 + 1 <= NBINS) {
        float d = (b0 + 1) * (CUTOFF_F / NBINS);
        g_tabh[(b0 + 1) * H + f] = __float2half(v1 * 0.5f * (cosf(d * (PI_F / CUTOFF_F)) + 1.f));
    }
}

// pack endpoint pairs: tab2[b][f] = (tab[b][f], tab[b+1][f])
__global__ void pack_pairs() {
    int idx = blockIdx.x * blockDim.x + threadIdx.x;
    if (idx < NBINS * H)
        g_tab2[idx] = __halves2half2(g_tabh[idx], g_tabh[idx + H]);
}

// ======================= Node GEMM =======================
#define GF_BIAS   1
#define GF_SSP    2
#define GF_ACC    8
#define GF_HALF   16

// shared inner product core: acc[4][4] over a 32-k chunk held in As/Ws
__device__ __forceinline__ void mma_core(
    float (*As)[36], float (*Ws)[128], unsigned long long (&acc)[4][4], int tx, int ty)
{
#pragma unroll
    for (int kk4 = 0; kk4 < 8; kk4++) {
        float4 av[4];
#pragma unroll
        for (int j = 0; j < 4; j++)
            av[j] = *(const float4*)&As[ty * 4 + j][kk4 * 4];
#pragma unroll
        for (int m = 0; m < 4; m++) {
            ulonglong2 w0 = *(const ulonglong2*)&Ws[kk4 * 4 + m][tx * 8];
            ulonglong2 w1 = *(const ulonglong2*)&Ws[kk4 * 4 + m][tx * 8 + 4];
#pragma unroll
            for (int j = 0; j < 4; j++) {
                float a = (m == 0) ? av[j].x : (m == 1) ? av[j].y : (m == 2) ? av[j].z : av[j].w;
                unsigned long long a2 = bcast2(a);
                fma2(acc[j][0], a2, w0.x);
                fma2(acc[j][1], a2, w0.y);
                fma2(acc[j][2], a2, w1.x);
                fma2(acc[j][3], a2, w1.y);
            }
        }
    }
}

template<int FLAGS>
__global__ void __launch_bounds__(128) gemmN(
    const float* __restrict__ A, const float* __restrict__ W,
    const float* __restrict__ bias, float* __restrict__ out, int M)
{
    __shared__ float As[32][36];
    __shared__ float Ws[32][128];
    int tid = threadIdx.x;
    int tx = tid & 15;
    int ty = tid >> 4;
    int r0 = blockIdx.x * 32;
    unsigned long long acc[4][4];
#pragma unroll
    for (int j = 0; j < 4; j++)
#pragma unroll
        for (int c = 0; c < 4; c++) acc[j][c] = 0ull;

    for (int k0 = 0; k0 < 128; k0 += 32) {
        __syncthreads();
#pragma unroll
        for (int rep = 0; rep < 2; rep++) {
            int idx = tid + rep * 128;
            int kkg = idx & 7, r = idx >> 3;
            int row = r0 + r;
            float4 v = (row < M) ? *(const float4*)&A[(size_t)row * 128 + k0 + kkg * 4]
                                 : make_float4(0.f, 0.f, 0.f, 0.f);
            *(float4*)&As[r][kkg * 4] = v;
        }
#pragma unroll
        for (int rep = 0; rep < 8; rep++) {
            int idx = tid + rep * 128;
            int cg = idx & 31, kk = idx >> 5;
            *(float4*)&Ws[kk][cg * 4] = *(const float4*)&W[(size_t)(k0 + kk) * 128 + cg * 4];
        }
        __syncthreads();
        mma_core(As, Ws, acc, tx, ty);
    }

    float bv[8];
    if (FLAGS & GF_BIAS) {
        float4 bq0 = *(const float4*)&bias[tx * 8];
        float4 bq1 = *(const float4*)&bias[tx * 8 + 4];
        bv[0]=bq0.x; bv[1]=bq0.y; bv[2]=bq0.z; bv[3]=bq0.w;
        bv[4]=bq1.x; bv[5]=bq1.y; bv[6]=bq1.z; bv[7]=bq1.w;
    } else {
#pragma unroll
        for (int i = 0; i < 8; i++) bv[i] = 0.f;
    }
#pragma unroll
    for (int j = 0; j < 4; j++) {
        int row = r0 + ty * 4 + j;
        if (row >= M) continue;
        float v[8];
#pragma unroll
        for (int c = 0; c < 4; c++) {
            float2 p = unpack2(acc[j][c]);
            v[c * 2] = p.x + bv[c * 2];
            v[c * 2 + 1] = p.y + bv[c * 2 + 1];
        }
        if (FLAGS & GF_SSP) {
#pragma unroll
            for (int i = 0; i < 8; i++) v[i] = sspf(v[i]);
        }
        if (FLAGS & GF_HALF) {
            uint4 o;
            o.x = h2_as_u32(__floats2half2_rn(v[0], v[1]));
            o.y = h2_as_u32(__floats2half2_rn(v[2], v[3]));
            o.z = h2_as_u32(__floats2half2_rn(v[4], v[5]));
            o.w = h2_as_u32(__floats2half2_rn(v[6], v[7]));
            *(uint4*)&((__half*)out)[(size_t)row * 128 + tx * 8] = o;
        } else if (FLAGS & GF_ACC) {
            float4* op0 = (float4*)&out[(size_t)row * 128 + tx * 8];
            float4* op1 = op0 + 1;
            float4 o0 = *op0, o1 = *op1;
            o0.x += v[0]; o0.y += v[1]; o0.z += v[2]; o0.w += v[3];
            o1.x += v[4]; o1.y += v[5]; o1.z += v[6]; o1.w += v[7];
            *op0 = o0; *op1 = o1;
        } else {
            *(float4*)&out[(size_t)row * 128 + tx * 8] = make_float4(v[0], v[1], v[2], v[3]);
            *(float4*)&out[(size_t)row * 128 + tx * 8 + 4] = make_float4(v[4], v[5], v[6], v[7]);
        }
    }
}

// Fused: h[rows] += ssp(agg@W2 + b2) @ W3 + b3   (stage-1 result kept in smem)
__global__ void __launch_bounds__(128) gemm_dual(
    const float* __restrict__ A, const float* __restrict__ W2, const float* __restrict__ b2,
    const float* __restrict__ W3, const float* __restrict__ b3,
    float* __restrict__ out, int M)
{
    __shared__ float As[32][36];
    __shared__ float Ws[32][128];
    __shared__ float Ts[32][132];
    int tid = threadIdx.x;
    int tx = tid & 15;
    int ty = tid >> 4;
    int r0 = blockIdx.x * 32;
    unsigned long long acc[4][4];
#pragma unroll
    for (int j = 0; j < 4; j++)
#pragma unroll
        for (int c = 0; c < 4; c++) acc[j][c] = 0ull;

    // ---- stage 1: t = ssp(agg @ W2 + b2) ----
    for (int k0 = 0; k0 < 128; k0 += 32) {
        __syncthreads();
#pragma unroll
        for (int rep = 0; rep < 2; rep++) {
            int idx = tid + rep * 128;
            int kkg = idx & 7, r = idx >> 3;
            int row = r0 + r;
            float4 v = (row < M) ? *(const float4*)&A[(size_t)row * 128 + k0 + kkg * 4]
                                 : make_float4(0.f, 0.f, 0.f, 0.f);
            *(float4*)&As[r][kkg * 4] = v;
        }
#pragma unroll
        for (int rep = 0; rep < 8; rep++) {
            int idx = tid + rep * 128;
            int cg = idx & 31, kk = idx >> 5;
            *(float4*)&Ws[kk][cg * 4] = *(const float4*)&W2[(size_t)(k0 + kk) * 128 + cg * 4];
        }
        __syncthreads();
        mma_core(As, Ws, acc, tx, ty);
    }
    {
        float4 bq0 = *(const float4*)&b2[tx * 8];
        float4 bq1 = *(const float4*)&b2[tx * 8 + 4];
        float bb[8] = {bq0.x, bq0.y, bq0.z, bq0.w, bq1.x, bq1.y, bq1.z, bq1.w};
        __syncthreads();
#pragma unroll
        for (int j = 0; j < 4; j++) {
            int r = ty * 4 + j;
#pragma unroll
            for (int c = 0; c < 4; c++) {
                float2 p = unpack2(acc[j][c]);
                Ts[r][tx * 8 + c * 2]     = sspf(p.x + bb[c * 2]);
                Ts[r][tx * 8 + c * 2 + 1] = sspf(p.y + bb[c * 2 + 1]);
                acc[j][c] = 0ull;
            }
        }
    }
    __syncthreads();

    // ---- stage 2: out += t @ W3 + b3 ----
    for (int k0 = 0; k0 < 128; k0 += 32) {
        __syncthreads();
#pragma unroll
        for (int rep = 0; rep < 8; rep++) {
            int idx = tid + rep * 128;
            int cg = idx & 31, kk = idx >> 5;
            *(float4*)&Ws[kk][cg * 4] = *(const float4*)&W3[(size_t)(k0 + kk) * 128 + cg * 4];
        }
        __syncthreads();
#pragma unroll
        for (int kk4 = 0; kk4 < 8; kk4++) {
            float4 av[4];
#pragma unroll
            for (int j = 0; j < 4; j++)
                av[j] = *(const float4*)&Ts[ty * 4 + j][k0 + kk4 * 4];
#pragma unroll
            for (int m = 0; m < 4; m++) {
                ulonglong2 w0 = *(const ulonglong2*)&Ws[kk4 * 4 + m][tx * 8];
                ulonglong2 w1 = *(const ulonglong2*)&Ws[kk4 * 4 + m][tx * 8 + 4];
#pragma unroll
                for (int j = 0; j < 4; j++) {
                    float a = (m == 0) ? av[j].x : (m == 1) ? av[j].y : (m == 2) ? av[j].z : av[j].w;
                    unsigned long long a2 = bcast2(a);
                    fma2(acc[j][0], a2, w0.x);
                    fma2(acc[j][1], a2, w0.y);
                    fma2(acc[j][2], a2, w1.x);
                    fma2(acc[j][3], a2, w1.y);
                }
            }
        }
    }
    {
        float4 bq0 = *(const float4*)&b3[tx * 8];
        float4 bq1 = *(const float4*)&b3[tx * 8 + 4];
        float bb[8] = {bq0.x, bq0.y, bq0.z, bq0.w, bq1.x, bq1.y, bq1.z, bq1.w};
#pragma unroll
        for (int j = 0; j < 4; j++) {
            int row = r0 + ty * 4 + j;
            if (row >= M) continue;
            float v[8];
#pragma unroll
            for (int c = 0; c < 4; c++) {
                float2 p = unpack2(acc[j][c]);
                v[c * 2]     = p.x + bb[c * 2];
                v[c * 2 + 1] = p.y + bb[c * 2 + 1];
            }
            float4* op0 = (float4*)&out[(size_t)row * 128 + tx * 8];
            float4* op1 = op0 + 1;
            float4 o0 = *op0, o1 = *op1;
            o0.x += v[0]; o0.y += v[1]; o0.z += v[2]; o0.w += v[3];
            o1.x += v[4]; o1.y += v[5]; o1.z += v[6]; o1.w += v[7];
            *op0 = o0; *op1 = o1;
        }
    }
}

// ======================= Edge gather (warp per dst node, packed table) =======================
__global__ void edge_gather(int N) {
    int warp = (blockIdx.x * blockDim.x + threadIdx.x) >> 5;
    int lane = threadIdx.x & 31;
    if (warp >= N) return;
    int beg = g_rowptr[warp], end = g_rowptr[warp + 1];
    float a0 = 0.f, a1 = 0.f, a2 = 0.f, a3 = 0.f;
#pragma unroll 4
    for (int i = beg; i < end; i++) {
        int2 sd = __ldg(&g_csr[i]);
        float d = __int_as_float(sd.y);
        float u = d * ((float)NBINS / CUTOFF_F);
        int i0 = min(max((int)u, 0), NBINS - 1);
        float fr = u - (float)i0;
        uint4 tp = *(const uint4*)&g_tab2[(size_t)i0 * H + lane * 4];
        uint2 xq = *(const uint2*)&g_xfh[(size_t)sd.x * H + lane * 4];
        float2 p0 = __half22float2(*(__half2*)&tp.x);
        float2 p1 = __half22float2(*(__half2*)&tp.y);
        float2 p2 = __half22float2(*(__half2*)&tp.z);
        float2 p3 = __half22float2(*(__half2*)&tp.w);
        float2 xa = __half22float2(*(__half2*)&xq.x);
        float2 xb = __half22float2(*(__half2*)&xq.y);
        a0 += xa.x * fmaf(fr, p0.y - p0.x, p0.x);
        a1 += xa.y * fmaf(fr, p1.y - p1.x, p1.x);
        a2 += xb.x * fmaf(fr, p2.y - p2.x, p2.x);
        a3 += xb.y * fmaf(fr, p3.y - p3.x, p3.x);
    }
    *(float4*)&g_agg[(size_t)warp * H + lane * 4] = make_float4(a0, a1, a2, a3);
}

// ======================= Readout =======================
__global__ void __launch_bounds__(256) readout_gemm(
    const float* __restrict__ A, const float* __restrict__ W,
    const float* __restrict__ bias, int M)
{
    constexpr int NCOL = 64;
    constexpr int CT = NCOL / 4;
    constexpr int ROWS = (256 / CT) * 4;
    __shared__ float As[ROWS][33];
    __shared__ float Ws[32][NCOL];
    __shared__ float csum[NCOL];
    int tid = threadIdx.x;
    int tx = tid % CT, ty = tid / CT;
    int r0 = blockIdx.x * ROWS;
    if (tid < NCOL) csum[tid] = 0.f;
    unsigned long long a01[4] = {0,0,0,0}, a23[4] = {0,0,0,0};
    for (int k0 = 0; k0 < 128; k0 += 32) {
        __syncthreads();
        for (int i = tid; i < ROWS * 32; i += 256) {
            int r = i >> 5, kk = i & 31;
            int row = r0 + r;
            As[r][kk] = (row < M) ? A[(size_t)row * 128 + k0 + kk] : 0.f;
        }
        for (int i = tid; i < 32 * NCOL; i += 256) {
            int kk = i / NCOL, c = i % NCOL;
            Ws[kk][c] = W[(size_t)(k0 + kk) * NCOL + c];
        }
        __syncthreads();
#pragma unroll
        for (int kk = 0; kk < 32; kk++) {
            ulonglong2 wv = *(const ulonglong2*)&Ws[kk][tx * 4];
#pragma unroll
            for (int i = 0; i < 4; i++) {
                unsigned long long a2 = bcast2(As[ty * 4 + i][kk]);
                fma2(a01[i], a2, wv.x);
                fma2(a23[i], a2, wv.y);
            }
        }
    }
    float4 bvq = *(const float4*)&bias[tx * 4];
#pragma unroll
    for (int i = 0; i < 4; i++) {
        int row = r0 + ty * 4 + i;
        if (row >= M) break;
        float2 p0 = unpack2(a01[i]);
        float2 p1 = unpack2(a23[i]);
        atomicAdd(&csum[tx * 4 + 0], sspf(p0.x + bvq.x));
        atomicAdd(&csum[tx * 4 + 1], sspf(p0.y + bvq.y));
        atomicAdd(&csum[tx * 4 + 2], sspf(p1.x + bvq.z));
        atomicAdd(&csum[tx * 4 + 3], sspf(p1.y + bvq.w));
    }
    __syncthreads();
    if (tid < NCOL) atomicAdd(&g_acc[tid], csum[tid]);
}

__global__ void readout_final(const float* __restrict__ o2w, const float* __restrict__ o2b,
                              const float* __restrict__ rw, const float* __restrict__ rb,
                              float* __restrict__ out, int N) {
    __shared__ float v[64];
    int t = threadIdx.x;
    float a = (float)N * o2b[t];
#pragma unroll 8
    for (int j = 0; j < 64; j++) a += g_acc[j] * o2w[j * 64 + t];
    v[t] = a;
    __syncthreads();
    if (t < 12) {
        float r = rb[t];
#pragma unroll
        for (int j = 0; j < 64; j++) r += v[j] * rw[j * 12 + t];
        out[t] = r;
    }
}

extern "C" void kernel_launch(void* const* d_in, const int* in_sizes, int n_in,
                              void* d_out, int out_size) {
    const int*   x    = (const int*)d_in[0];
    const int*   ei   = (const int*)d_in[1];
    const float* dist = (const float*)d_in[2];
    const float* emb  = (const float*)d_in[3];
    const float* mw1  = (const float*)d_in[4];
    const float* mb1  = (const float*)d_in[5];
    const float* mw2  = (const float*)d_in[6];
    const float* mb2  = (const float*)d_in[7];
    const float* l1w  = (const float*)d_in[8];
    const float* l2w  = (const float*)d_in[9];
    const float* l2b  = (const float*)d_in[10];
    const float* lw   = (const float*)d_in[11];
    const float* lb   = (const float*)d_in[12];
    const float* o1w  = (const float*)d_in[13];
    const float* o1b  = (const float*)d_in[14];
    const float* o2w  = (const float*)d_in[15];
    const float* o2b  = (const float*)d_in[16];
    const float* rw   = (const float*)d_in[17];
    const float* rb   = (const float*)d_in[18];

    int N = in_sizes[0];
    int E = in_sizes[2];
    int L = in_sizes[4] / (G * H);

    float *pacc;
    int *prow, *pcur;
    cudaGetSymbolAddress((void**)&pacc, g_acc);
    cudaGetSymbolAddress((void**)&prow, g_rowptr);
    cudaGetSymbolAddress((void**)&pcur, g_cursor);
    float *ph, *pxfh, *pagg;
    cudaGetSymbolAddress((void**)&ph, g_h);
    cudaGetSymbolAddress((void**)&pxfh, g_xfh);
    cudaGetSymbolAddress((void**)&pagg, g_agg);

    // side stream + events for graph-parallel branches (created once)
    static cudaStream_t s2 = nullptr;
    static cudaEvent_t evF = nullptr, evJ = nullptr;
    if (!s2) {
        cudaStreamCreateWithFlags(&s2, cudaStreamNonBlocking);
        cudaEventCreateWithFlags(&evF, cudaEventDisableTiming);
        cudaEventCreateWithFlags(&evJ, cudaEventDisableTiming);
    }

    const int* esrc = ei;
    const int* edst = ei + E;

    embed_kernel<<<N, 128>>>(x, emb, N);

    // ---- CSR build (once) ----
    cudaMemsetAsync(prow, 0, (N + 1) * sizeof(int));
    hist_kernel<<<(E + 255) / 256, 256>>>(edst, E);
    scan_kernel<<<1, 1024>>>(N + 1);
    cudaMemcpyAsync(pcur, prow, N * sizeof(int), cudaMemcpyDeviceToDevice);
    scatter_kernel<<<(E + 255) / 256, 256>>>(esrc, edst, dist, E);

    int nbN = (N + 31) / 32;
    int nbE = (N + 7) / 8;
    int nbT = (NBINS + 2) / 2;

    for (int l = 0; l < L; l++) {
        // fork: table build on s2, xf GEMM on main
        cudaEventRecord(evF, 0);
        cudaStreamWaitEvent(s2, evF, 0);
        table_fused<<<nbT, 128, 0, s2>>>(mw1 + (size_t)l * G * H, mb1 + (size_t)l * H,
                                         mw2 + (size_t)l * H * H, mb2 + (size_t)l * H);
        pack_pairs<<<(NBINS * H + 255) / 256, 256, 0, s2>>>();
        cudaEventRecord(evJ, s2);

        gemmN<GF_HALF><<<nbN, 128>>>(ph, l1w + (size_t)l * H * H, nullptr, (float*)pxfh, N);

        cudaStreamWaitEvent(0, evJ, 0);
        edge_gather<<<nbE, 256>>>(N);
        gemm_dual<<<nbN, 128>>>(pagg, l2w + (size_t)l * H * H, l2b + (size_t)l * H,
                                lw + (size_t)l * H * H, lb + (size_t)l * H, ph, N);
    }

    cudaMemsetAsync(pacc, 0, 64 * sizeof(float));
    readout_gemm<<<(N + 63) / 64, 256>>>(ph, o1w, o1b, N);
    readout_final<<<1, 64>>>(o2w, o2b, rw, rb, (float*)d_out, N);
}

// round 6
// speedup vs baseline: 1.0756x; 1.0756x over previous
#include <cuda_runtime.h>
#include <cuda_fp16.h>
#include <math.h>

#define H 128
#define G 50
#define NBINS 1024
#define CUTOFF_F 10.0f
#define NMAX 10000
#define EMAX 320000
#define PI_F 3.14159265358979323846f

__device__ __align__(16) float  g_h[NMAX * H];
__device__ __align__(16) __half g_xfh[NMAX * H];
__device__ __align__(16) float  g_agg[NMAX * H];
__device__ __align__(16) __half2 g_tab2[NBINS * H];   // [b][f] = (W[b][f], W[b+1][f])
__device__ float g_acc[64];
__device__ int  g_rowptr[NMAX + 1];
__device__ int  g_cursor[NMAX];
__device__ __align__(16) int2 g_csr[EMAX];

__device__ __forceinline__ float sspf(float x) {
    return fmaxf(x, 0.f) + log1pf(expf(-fabsf(x))) - 0.69314718055994530942f;
}
__device__ __forceinline__ unsigned int h2_as_u32(__half2 h) {
    return *reinterpret_cast<unsigned int*>(&h);
}

// ---- f32x2 packed-FMA helpers ----
__device__ __forceinline__ void fma2(unsigned long long& d, unsigned long long a, unsigned long long b) {
    asm("fma.rn.f32x2 %0, %1, %2, %0;" : "+l"(d) : "l"(a), "l"(b));
}
__device__ __forceinline__ unsigned long long bcast2(float a) {
    unsigned long long r; asm("mov.b64 %0, {%1, %1};" : "=l"(r) : "f"(a)); return r;
}
__device__ __forceinline__ unsigned long long pack2(float a, float b) {
    unsigned long long r; asm("mov.b64 %0, {%1, %2};" : "=l"(r) : "f"(a), "f"(b)); return r;
}
__device__ __forceinline__ float2 unpack2(unsigned long long v) {
    float2 f; asm("mov.b64 {%0, %1}, %2;" : "=f"(f.x), "=f"(f.y) : "l"(v)); return f;
}

__global__ void embed_kernel(const int* __restrict__ x, const float* __restrict__ emb, int N) {
    int n = blockIdx.x;
    if (n < N) g_h[n * H + threadIdx.x] = emb[x[n] * H + threadIdx.x];
}

// ======================= CSR build =======================
__global__ void hist_kernel(const int* __restrict__ dst, int E) {
    int e = blockIdx.x * blockDim.x + threadIdx.x;
    if (e < E) atomicAdd(&g_rowptr[dst[e] + 1], 1);
}

__global__ void __launch_bounds__(1024) scan_kernel(int n) {
    __shared__ int sums[1024];
    int t = threadIdx.x;
    int C = (n + 1023) / 1024;
    int local[12];
    int base = t * C;
    int s = 0;
#pragma unroll
    for (int i = 0; i < 12; i++) {
        if (i >= C) break;
        int idx = base + i;
        int v = (idx < n) ? g_rowptr[idx] : 0;
        s += v; local[i] = s;
    }
    sums[t] = s;
    __syncthreads();
    for (int off = 1; off < 1024; off <<= 1) {
        int v = (t >= off) ? sums[t - off] : 0;
        __syncthreads();
        sums[t] += v;
        __syncthreads();
    }
    int prev = (t > 0) ? sums[t - 1] : 0;
#pragma unroll
    for (int i = 0; i < 12; i++) {
        if (i >= C) break;
        int idx = base + i;
        if (idx < n) g_rowptr[idx] = local[i] + prev;
    }
}

__global__ void scatter_kernel(const int* __restrict__ src, const int* __restrict__ dst,
                               const float* __restrict__ dist, int E) {
    int e = blockIdx.x * blockDim.x + threadIdx.x;
    if (e < E) {
        int p = atomicAdd(&g_cursor[dst[e]], 1);
        g_csr[p] = make_int2(src[e], __float_as_int(dist[e]));
    }
}

// ======================= Fused filter-table build (writes lerp pairs directly) ====
// Block computes 3 bins b0,b0+1,b0+2 and writes pairs for b0 and b0+1.
__global__ void __launch_bounds__(128) table_fused(
    const float* __restrict__ w1, const float* __restrict__ b1,
    const float* __restrict__ w2, const float* __restrict__ b2)
{
    __shared__ float a_s[3][H];
    __shared__ float eas[3][G];
    int f = threadIdx.x;
    int b0 = blockIdx.x * 2;
    const float spacing = CUTOFF_F / (G - 1);
    const float coeff = -0.5f / (spacing * spacing);
    // 3*G = 150 gaussian values; 128 threads -> two passes
    for (int i = f; i < 3 * G; i += 128) {
        int bi = i / G, g = i - bi * G;
        float d = (b0 + bi) * (CUTOFF_F / NBINS);
        float dd = d - g * spacing;
        eas[bi][g] = expf(coeff * dd * dd);
    }
    __syncthreads();
    float bv = b1[f];
    float a0 = bv, a1 = bv, a2 = bv;
#pragma unroll
    for (int g = 0; g < G; g++) {
        float w = w1[g * H + f];
        a0 += eas[0][g] * w;
        a1 += eas[1][g] * w;
        a2 += eas[2][g] * w;
    }
    a_s[0][f] = sspf(a0);
    a_s[1][f] = sspf(a1);
    a_s[2][f] = sspf(a2);
    __syncthreads();
    unsigned long long acc01 = 0ull;   // bins b0, b0+1
    float accc = 0.f;                  // bin b0+2
#pragma unroll 8
    for (int j = 0; j < H; j++) {
        float w = w2[j * H + f];
        fma2(acc01, pack2(a_s[0][j], a_s[1][j]), bcast2(w));
        accc = fmaf(a_s[2][j], w, accc);
    }
    float2 v01 = unpack2(acc01);
    float b2v = b2[f];
    float v0 = v01.x + b2v, v1 = v01.y + b2v, v2 = accc + b2v;
    float d0 = b0 * (CUTOFF_F / NBINS);
    float d1 = (b0 + 1) * (CUTOFF_F / NBINS);
    float d2 = (b0 + 2) * (CUTOFF_F / NBINS);
    v0 *= 0.5f * (cosf(d0 * (PI_F / CUTOFF_F)) + 1.f);
    v1 *= 0.5f * (cosf(d1 * (PI_F / CUTOFF_F)) + 1.f);
    v2 *= 0.5f * (cosf(d2 * (PI_F / CUTOFF_F)) + 1.f);
    g_tab2[b0 * H + f]       = __floats2half2_rn(v0, v1);
    if (b0 + 1 < NBINS)
        g_tab2[(b0 + 1) * H + f] = __floats2half2_rn(v1, v2);
}

// ======================= Node GEMM =======================
#define GF_BIAS   1
#define GF_SSP    2
#define GF_ACC    8
#define GF_HALF   16

__device__ __forceinline__ void mma_core(
    float (*As)[36], float (*Ws)[128], unsigned long long (&acc)[4][4], int tx, int ty)
{
#pragma unroll
    for (int kk4 = 0; kk4 < 8; kk4++) {
        float4 av[4];
#pragma unroll
        for (int j = 0; j < 4; j++)
            av[j] = *(const float4*)&As[ty * 4 + j][kk4 * 4];
#pragma unroll
        for (int m = 0; m < 4; m++) {
            ulonglong2 w0 = *(const ulonglong2*)&Ws[kk4 * 4 + m][tx * 8];
            ulonglong2 w1 = *(const ulonglong2*)&Ws[kk4 * 4 + m][tx * 8 + 4];
#pragma unroll
            for (int j = 0; j < 4; j++) {
                float a = (m == 0) ? av[j].x : (m == 1) ? av[j].y : (m == 2) ? av[j].z : av[j].w;
                unsigned long long a2 = bcast2(a);
                fma2(acc[j][0], a2, w0.x);
                fma2(acc[j][1], a2, w0.y);
                fma2(acc[j][2], a2, w1.x);
                fma2(acc[j][3], a2, w1.y);
            }
        }
    }
}

template<int FLAGS>
__global__ void __launch_bounds__(128) gemmN(
    const float* __restrict__ A, const float* __restrict__ W,
    const float* __restrict__ bias, float* __restrict__ out, int M)
{
    __shared__ float As[32][36];
    __shared__ float Ws[32][128];
    int tid = threadIdx.x;
    int tx = tid & 15;
    int ty = tid >> 4;
    int r0 = blockIdx.x * 32;
    unsigned long long acc[4][4];
#pragma unroll
    for (int j = 0; j < 4; j++)
#pragma unroll
        for (int c = 0; c < 4; c++) acc[j][c] = 0ull;

    for (int k0 = 0; k0 < 128; k0 += 32) {
        __syncthreads();
#pragma unroll
        for (int rep = 0; rep < 2; rep++) {
            int idx = tid + rep * 128;
            int kkg = idx & 7, r = idx >> 3;
            int row = r0 + r;
            float4 v = (row < M) ? *(const float4*)&A[(size_t)row * 128 + k0 + kkg * 4]
                                 : make_float4(0.f, 0.f, 0.f, 0.f);
            *(float4*)&As[r][kkg * 4] = v;
        }
#pragma unroll
        for (int rep = 0; rep < 8; rep++) {
            int idx = tid + rep * 128;
            int cg = idx & 31, kk = idx >> 5;
            *(float4*)&Ws[kk][cg * 4] = *(const float4*)&W[(size_t)(k0 + kk) * 128 + cg * 4];
        }
        __syncthreads();
        mma_core(As, Ws, acc, tx, ty);
    }

    float bv[8];
    if (FLAGS & GF_BIAS) {
        float4 bq0 = *(const float4*)&bias[tx * 8];
        float4 bq1 = *(const float4*)&bias[tx * 8 + 4];
        bv[0]=bq0.x; bv[1]=bq0.y; bv[2]=bq0.z; bv[3]=bq0.w;
        bv[4]=bq1.x; bv[5]=bq1.y; bv[6]=bq1.z; bv[7]=bq1.w;
    } else {
#pragma unroll
        for (int i = 0; i < 8; i++) bv[i] = 0.f;
    }
#pragma unroll
    for (int j = 0; j < 4; j++) {
        int row = r0 + ty * 4 + j;
        if (row >= M) continue;
        float v[8];
#pragma unroll
        for (int c = 0; c < 4; c++) {
            float2 p = unpack2(acc[j][c]);
            v[c * 2] = p.x + bv[c * 2];
            v[c * 2 + 1] = p.y + bv[c * 2 + 1];
        }
        if (FLAGS & GF_SSP) {
#pragma unroll
            for (int i = 0; i < 8; i++) v[i] = sspf(v[i]);
        }
        if (FLAGS & GF_HALF) {
            uint4 o;
            o.x = h2_as_u32(__floats2half2_rn(v[0], v[1]));
            o.y = h2_as_u32(__floats2half2_rn(v[2], v[3]));
            o.z = h2_as_u32(__floats2half2_rn(v[4], v[5]));
            o.w = h2_as_u32(__floats2half2_rn(v[6], v[7]));
            *(uint4*)&((__half*)out)[(size_t)row * 128 + tx * 8] = o;
        } else if (FLAGS & GF_ACC) {
            float4* op0 = (float4*)&out[(size_t)row * 128 + tx * 8];
            float4* op1 = op0 + 1;
            float4 o0 = *op0, o1 = *op1;
            o0.x += v[0]; o0.y += v[1]; o0.z += v[2]; o0.w += v[3];
            o1.x += v[4]; o1.y += v[5]; o1.z += v[6]; o1.w += v[7];
            *op0 = o0; *op1 = o1;
        } else {
            *(float4*)&out[(size_t)row * 128 + tx * 8] = make_float4(v[0], v[1], v[2], v[3]);
            *(float4*)&out[(size_t)row * 128 + tx * 8 + 4] = make_float4(v[4], v[5], v[6], v[7]);
        }
    }
}

// Fused: h[rows] += ssp(agg@W2 + b2) @ W3 + b3   (stage-1 result kept in smem)
__global__ void __launch_bounds__(128) gemm_dual(
    const float* __restrict__ A, const float* __restrict__ W2, const float* __restrict__ b2,
    const float* __restrict__ W3, const float* __restrict__ b3,
    float* __restrict__ out, int M)
{
    __shared__ float As[32][36];
    __shared__ float Ws[32][128];
    __shared__ float Ts[32][132];
    int tid = threadIdx.x;
    int tx = tid & 15;
    int ty = tid >> 4;
    int r0 = blockIdx.x * 32;
    unsigned long long acc[4][4];
#pragma unroll
    for (int j = 0; j < 4; j++)
#pragma unroll
        for (int c = 0; c < 4; c++) acc[j][c] = 0ull;

    for (int k0 = 0; k0 < 128; k0 += 32) {
        __syncthreads();
#pragma unroll
        for (int rep = 0; rep < 2; rep++) {
            int idx = tid + rep * 128;
            int kkg = idx & 7, r = idx >> 3;
            int row = r0 + r;
            float4 v = (row < M) ? *(const float4*)&A[(size_t)row * 128 + k0 + kkg * 4]
                                 : make_float4(0.f, 0.f, 0.f, 0.f);
            *(float4*)&As[r][kkg * 4] = v;
        }
#pragma unroll
        for (int rep = 0; rep < 8; rep++) {
            int idx = tid + rep * 128;
            int cg = idx & 31, kk = idx >> 5;
            *(float4*)&Ws[kk][cg * 4] = *(const float4*)&W2[(size_t)(k0 + kk) * 128 + cg * 4];
        }
        __syncthreads();
        mma_core(As, Ws, acc, tx, ty);
    }
    {
        float4 bq0 = *(const float4*)&b2[tx * 8];
        float4 bq1 = *(const float4*)&b2[tx * 8 + 4];
        float bb[8] = {bq0.x, bq0.y, bq0.z, bq0.w, bq1.x, bq1.y, bq1.z, bq1.w};
        __syncthreads();
#pragma unroll
        for (int j = 0; j < 4; j++) {
            int r = ty * 4 + j;
#pragma unroll
            for (int c = 0; c < 4; c++) {
                float2 p = unpack2(acc[j][c]);
                Ts[r][tx * 8 + c * 2]     = sspf(p.x + bb[c * 2]);
                Ts[r][tx * 8 + c * 2 + 1] = sspf(p.y + bb[c * 2 + 1]);
                acc[j][c] = 0ull;
            }
        }
    }
    __syncthreads();

    for (int k0 = 0; k0 < 128; k0 += 32) {
        __syncthreads();
#pragma unroll
        for (int rep = 0; rep < 8; rep++) {
            int idx = tid + rep * 128;
            int cg = idx & 31, kk = idx >> 5;
            *(float4*)&Ws[kk][cg * 4] = *(const float4*)&W3[(size_t)(k0 + kk) * 128 + cg * 4];
        }
        __syncthreads();
#pragma unroll
        for (int kk4 = 0; kk4 < 8; kk4++) {
            float4 av[4];
#pragma unroll
            for (int j = 0; j < 4; j++)
                av[j] = *(const float4*)&Ts[ty * 4 + j][k0 + kk4 * 4];
#pragma unroll
            for (int m = 0; m < 4; m++) {
                ulonglong2 w0 = *(const ulonglong2*)&Ws[kk4 * 4 + m][tx * 8];
                ulonglong2 w1 = *(const ulonglong2*)&Ws[kk4 * 4 + m][tx * 8 + 4];
#pragma unroll
                for (int j = 0; j < 4; j++) {
                    float a = (m == 0) ? av[j].x : (m == 1) ? av[j].y : (m == 2) ? av[j].z : av[j].w;
                    unsigned long long a2 = bcast2(a);
                    fma2(acc[j][0], a2, w0.x);
                    fma2(acc[j][1], a2, w0.y);
                    fma2(acc[j][2], a2, w1.x);
                    fma2(acc[j][3], a2, w1.y);
                }
            }
        }
    }
    {
        float4 bq0 = *(const float4*)&b3[tx * 8];
        float4 bq1 = *(const float4*)&b3[tx * 8 + 4];
        float bb[8] = {bq0.x, bq0.y, bq0.z, bq0.w, bq1.x, bq1.y, bq1.z, bq1.w};
#pragma unroll
        for (int j = 0; j < 4; j++) {
            int row = r0 + ty * 4 + j;
            if (row >= M) continue;
            float v[8];
#pragma unroll
            for (int c = 0; c < 4; c++) {
                float2 p = unpack2(acc[j][c]);
                v[c * 2]     = p.x + bb[c * 2];
                v[c * 2 + 1] = p.y + bb[c * 2 + 1];
            }
            float4* op0 = (float4*)&out[(size_t)row * 128 + tx * 8];
            float4* op1 = op0 + 1;
            float4 o0 = *op0, o1 = *op1;
            o0.x += v[0]; o0.y += v[1]; o0.z += v[2]; o0.w += v[3];
            o1.x += v[4]; o1.y += v[5]; o1.z += v[6]; o1.w += v[7];
            *op0 = o0; *op1 = o1;
        }
    }
}

// ======================= Edge gather (warp per dst node, packed table) =======================
__global__ void edge_gather(int N) {
    int warp = (blockIdx.x * blockDim.x + threadIdx.x) >> 5;
    int lane = threadIdx.x & 31;
    if (warp >= N) return;
    int beg = g_rowptr[warp], end = g_rowptr[warp + 1];
    float a0 = 0.f, a1 = 0.f, a2 = 0.f, a3 = 0.f;
#pragma unroll 4
    for (int i = beg; i < end; i++) {
        int2 sd = g_csr[i];
        float d = __int_as_float(sd.y);
        float u = d * ((float)NBINS / CUTOFF_F);
        int i0 = min(max((int)u, 0), NBINS - 1);
        float fr = u - (float)i0;
        uint4 tp = *(const uint4*)&g_tab2[(size_t)i0 * H + lane * 4];
        uint2 xq = *(const uint2*)&g_xfh[(size_t)sd.x * H + lane * 4];
        float2 p0 = __half22float2(*(__half2*)&tp.x);
        float2 p1 = __half22float2(*(__half2*)&tp.y);
        float2 p2 = __half22float2(*(__half2*)&tp.z);
        float2 p3 = __half22float2(*(__half2*)&tp.w);
        float2 xa = __half22float2(*(__half2*)&xq.x);
        float2 xb = __half22float2(*(__half2*)&xq.y);
        a0 += xa.x * fmaf(fr, p0.y - p0.x, p0.x);
        a1 += xa.y * fmaf(fr, p1.y - p1.x, p1.x);
        a2 += xb.x * fmaf(fr, p2.y - p2.x, p2.x);
        a3 += xb.y * fmaf(fr, p3.y - p3.x, p3.x);
    }
    *(float4*)&g_agg[(size_t)warp * H + lane * 4] = make_float4(a0, a1, a2, a3);
}

// ======================= Readout =======================
__global__ void __launch_bounds__(256) readout_gemm(
    const float* __restrict__ A, const float* __restrict__ W,
    const float* __restrict__ bias, int M)
{
    constexpr int NCOL = 64;
    constexpr int CT = NCOL / 4;
    constexpr int ROWS = (256 / CT) * 4;
    __shared__ float As[ROWS][33];
    __shared__ float Ws[32][NCOL];
    __shared__ float csum[NCOL];
    int tid = threadIdx.x;
    int tx = tid % CT, ty = tid / CT;
    int r0 = blockIdx.x * ROWS;
    if (tid < NCOL) csum[tid] = 0.f;
    unsigned long long a01[4] = {0,0,0,0}, a23[4] = {0,0,0,0};
    for (int k0 = 0; k0 < 128; k0 += 32) {
        __syncthreads();
        for (int i = tid; i < ROWS * 32; i += 256) {
            int r = i >> 5, kk = i & 31;
            int row = r0 + r;
            As[r][kk] = (row < M) ? A[(size_t)row * 128 + k0 + kk] : 0.f;
        }
        for (int i = tid; i < 32 * NCOL; i += 256) {
            int kk = i / NCOL, c = i % NCOL;
            Ws[kk][c] = W[(size_t)(k0 + kk) * NCOL + c];
        }
        __syncthreads();
#pragma unroll
        for (int kk = 0; kk < 32; kk++) {
            ulonglong2 wv = *(const ulonglong2*)&Ws[kk][tx * 4];
#pragma unroll
            for (int i = 0; i < 4; i++) {
                unsigned long long a2 = bcast2(As[ty * 4 + i][kk]);
                fma2(a01[i], a2, wv.x);
                fma2(a23[i], a2, wv.y);
            }
        }
    }
    float4 bvq = *(const float4*)&bias[tx * 4];
#pragma unroll
    for (int i = 0; i < 4; i++) {
        int row = r0 + ty * 4 + i;
        if (row >= M) break;
        float2 p0 = unpack2(a01[i]);
        float2 p1 = unpack2(a23[i]);
        atomicAdd(&csum[tx * 4 + 0], sspf(p0.x + bvq.x));
        atomicAdd(&csum[tx * 4 + 1], sspf(p0.y + bvq.y));
        atomicAdd(&csum[tx * 4 + 2], sspf(p1.x + bvq.z));
        atomicAdd(&csum[tx * 4 + 3], sspf(p1.y + bvq.w));
    }
    __syncthreads();
    if (tid < NCOL) atomicAdd(&g_acc[tid], csum[tid]);
}

__global__ void readout_final(const float* __restrict__ o2w, const float* __restrict__ o2b,
                              const float* __restrict__ rw, const float* __restrict__ rb,
                              float* __restrict__ out, int N) {
    __shared__ float v[64];
    int t = threadIdx.x;
    float a = (float)N * o2b[t];
#pragma unroll 8
    for (int j = 0; j < 64; j++) a += g_acc[j] * o2w[j * 64 + t];
    v[t] = a;
    __syncthreads();
    if (t < 12) {
        float r = rb[t];
#pragma unroll
        for (int j = 0; j < 64; j++) r += v[j] * rw[j * 12 + t];
        out[t] = r;
    }
}

extern "C" void kernel_launch(void* const* d_in, const int* in_sizes, int n_in,
                              void* d_out, int out_size) {
    const int*   x    = (const int*)d_in[0];
    const int*   ei   = (const int*)d_in[1];
    const float* dist = (const float*)d_in[2];
    const float* emb  = (const float*)d_in[3];
    const float* mw1  = (const float*)d_in[4];
    const float* mb1  = (const float*)d_in[5];
    const float* mw2  = (const float*)d_in[6];
    const float* mb2  = (const float*)d_in[7];
    const float* l1w  = (const float*)d_in[8];
    const float* l2w  = (const float*)d_in[9];
    const float* l2b  = (const float*)d_in[10];
    const float* lw   = (const float*)d_in[11];
    const float* lb   = (const float*)d_in[12];
    const float* o1w  = (const float*)d_in[13];
    const float* o1b  = (const float*)d_in[14];
    const float* o2w  = (const float*)d_in[15];
    const float* o2b  = (const float*)d_in[16];
    const float* rw   = (const float*)d_in[17];
    const float* rb   = (const float*)d_in[18];

    int N = in_sizes[0];
    int E = in_sizes[2];
    int L = in_sizes[4] / (G * H);

    float *pacc;
    int *prow, *pcur;
    cudaGetSymbolAddress((void**)&pacc, g_acc);
    cudaGetSymbolAddress((void**)&prow, g_rowptr);
    cudaGetSymbolAddress((void**)&pcur, g_cursor);
    float *ph, *pxfh, *pagg;
    cudaGetSymbolAddress((void**)&ph, g_h);
    cudaGetSymbolAddress((void**)&pxfh, g_xfh);
    cudaGetSymbolAddress((void**)&pagg, g_agg);

    const int* esrc = ei;
    const int* edst = ei + E;

    embed_kernel<<<N, 128>>>(x, emb, N);

    // ---- CSR build (once) ----
    cudaMemsetAsync(prow, 0, (N + 1) * sizeof(int));
    hist_kernel<<<(E + 255) / 256, 256>>>(edst, E);
    scan_kernel<<<1, 1024>>>(N + 1);
    cudaMemcpyAsync(pcur, prow, N * sizeof(int), cudaMemcpyDeviceToDevice);
    scatter_kernel<<<(E + 255) / 256, 256>>>(esrc, edst, dist, E);

    int nbN = (N + 31) / 32;
    int nbE = (N + 7) / 8;
    int nbT = NBINS / 2;

    for (int l = 0; l < L; l++) {
        table_fused<<<nbT, 128>>>(mw1 + (size_t)l * G * H, mb1 + (size_t)l * H,
                                  mw2 + (size_t)l * H * H, mb2 + (size_t)l * H);
        gemmN<GF_HALF><<<nbN, 128>>>(ph, l1w + (size_t)l * H * H, nullptr, (float*)pxfh, N);
        edge_gather<<<nbE, 256>>>(N);
        gemm_dual<<<nbN, 128>>>(pagg, l2w + (size_t)l * H * H, l2b + (size_t)l * H,
                                lw + (size_t)l * H * H, lb + (size_t)l * H, ph, N);
    }

    cudaMemsetAsync(pacc, 0, 64 * sizeof(float));
    readout_gemm<<<(N + 63) / 64, 256>>>(ph, o1w, o1b, N);
    readout_final<<<1, 64>>>(o2w, o2b, rw, rb, (float*)d_out, N);
}

// round 7
// speedup vs baseline: 1.8280x; 1.6994x over previous
#include <cuda_runtime.h>
#include <cuda_fp16.h>
#include <math.h>

#define H 128
#define G 50
#define NBINS 1024
#define CUTOFF_F 10.0f
#define NMAX 10000
#define EMAX 320000
#define LMAX 6
#define PI_F 3.14159265358979323846f

__device__ __align__(16) float  g_h[NMAX * H];
__device__ __align__(16) __half g_xfh[NMAX * H];
__device__ __align__(16) float  g_agg[NMAX * H];
__device__ __align__(16) __half2 g_tab2[NBINS * H];   // [b][f] = (W[b][f], W[b+1][f])
__device__ float g_acc[64];
__device__ int  g_rowptr[NMAX + 1];
__device__ int  g_cursor[NMAX];
__device__ __align__(16) int2 g_csr[EMAX];
// pre-transposed fp16 weights: [l][n][k]
__device__ __align__(16) __half g_w1t[LMAX * H * H];
__device__ __align__(16) __half g_w2t[LMAX * H * H];
__device__ __align__(16) __half g_w3t[LMAX * H * H];

__device__ __forceinline__ float sspf(float x) {
    return fmaxf(x, 0.f) + log1pf(expf(-fabsf(x))) - 0.69314718055994530942f;
}

// ---- f32x2 packed-FMA helpers (table build) ----
__device__ __forceinline__ void fma2(unsigned long long& d, unsigned long long a, unsigned long long b) {
    asm("fma.rn.f32x2 %0, %1, %2, %0;" : "+l"(d) : "l"(a), "l"(b));
}
__device__ __forceinline__ unsigned long long bcast2(float a) {
    unsigned long long r; asm("mov.b64 %0, {%1, %1};" : "=l"(r) : "f"(a)); return r;
}
__device__ __forceinline__ unsigned long long pack2(float a, float b) {
    unsigned long long r; asm("mov.b64 %0, {%1, %2};" : "=l"(r) : "f"(a), "f"(b)); return r;
}
__device__ __forceinline__ float2 unpack2(unsigned long long v) {
    float2 f; asm("mov.b64 {%0, %1}, %2;" : "=f"(f.x), "=f"(f.y) : "l"(v)); return f;
}

// ---- HMMA m16n8k16 fp16 -> fp32 ----
__device__ __forceinline__ void hmma16816(float& c0, float& c1, float& c2, float& c3,
                                          unsigned a0, unsigned a1, unsigned a2, unsigned a3,
                                          unsigned b0, unsigned b1) {
    asm volatile(
        "mma.sync.aligned.m16n8k16.row.col.f32.f16.f16.f32 "
        "{%0,%1,%2,%3}, {%4,%5,%6,%7}, {%8,%9}, {%0,%1,%2,%3};"
        : "+f"(c0), "+f"(c1), "+f"(c2), "+f"(c3)
        : "r"(a0), "r"(a1), "r"(a2), "r"(a3), "r"(b0), "r"(b1));
}

// convert + transpose weights: out[l][n][k] = in[l][k][n] as fp16
__global__ void convert_weights(const float* __restrict__ w1, const float* __restrict__ w2,
                                const float* __restrict__ w3, int L) {
    int total = L * H * H;
    for (int idx = blockIdx.x * blockDim.x + threadIdx.x; idx < total; idx += gridDim.x * blockDim.x) {
        int l = idx >> 14;
        int r = idx & 16383;
        int k = r >> 7, n = r & 127;   // reading in[l][k][n] coalesced over n
        int o = (l << 14) + (n << 7) + k;
        g_w1t[o] = __float2half(w1[idx]);
        g_w2t[o] = __float2half(w2[idx]);
        g_w3t[o] = __float2half(w3[idx]);
    }
}

__global__ void embed_kernel(const int* __restrict__ x, const float* __restrict__ emb, int N) {
    int n = blockIdx.x;
    if (n < N) g_h[n * H + threadIdx.x] = emb[x[n] * H + threadIdx.x];
}

// ======================= CSR build =======================
__global__ void hist_kernel(const int* __restrict__ dst, int E) {
    int e = blockIdx.x * blockDim.x + threadIdx.x;
    if (e < E) atomicAdd(&g_rowptr[dst[e] + 1], 1);
}

__global__ void __launch_bounds__(1024) scan_kernel(int n) {
    __shared__ int sums[1024];
    int t = threadIdx.x;
    int C = (n + 1023) / 1024;
    int local[12];
    int base = t * C;
    int s = 0;
#pragma unroll
    for (int i = 0; i < 12; i++) {
        if (i >= C) break;
        int idx = base + i;
        int v = (idx < n) ? g_rowptr[idx] : 0;
        s += v; local[i] = s;
    }
    sums[t] = s;
    __syncthreads();
    for (int off = 1; off < 1024; off <<= 1) {
        int v = (t >= off) ? sums[t - off] : 0;
        __syncthreads();
        sums[t] += v;
        __syncthreads();
    }
    int prev = (t > 0) ? sums[t - 1] : 0;
#pragma unroll
    for (int i = 0; i < 12; i++) {
        if (i >= C) break;
        int idx = base + i;
        if (idx < n) {
            int v = local[i] + prev;
            g_rowptr[idx] = v;
            if (idx < n - 1) g_cursor[idx] = v;
        }
    }
}

__global__ void scatter_kernel(const int* __restrict__ src, const int* __restrict__ dst,
                               const float* __restrict__ dist, int E) {
    int e = blockIdx.x * blockDim.x + threadIdx.x;
    if (e < E) {
        int p = atomicAdd(&g_cursor[dst[e]], 1);
        g_csr[p] = make_int2(src[e], __float_as_int(dist[e]));
    }
}

// ======================= Fused filter-table build (writes lerp pairs directly) ====
__global__ void __launch_bounds__(128) table_fused(
    const float* __restrict__ w1, const float* __restrict__ b1,
    const float* __restrict__ w2, const float* __restrict__ b2)
{
    __shared__ float a_s[3][H];
    __shared__ float eas[3][G];
    int f = threadIdx.x;
    int b0 = blockIdx.x * 2;
    const float spacing = CUTOFF_F / (G - 1);
    const float coeff = -0.5f / (spacing * spacing);
    for (int i = f; i < 3 * G; i += 128) {
        int bi = i / G, g = i - bi * G;
        float d = (b0 + bi) * (CUTOFF_F / NBINS);
        float dd = d - g * spacing;
        eas[bi][g] = expf(coeff * dd * dd);
    }
    __syncthreads();
    float bv = b1[f];
    float a0 = bv, a1 = bv, a2 = bv;
#pragma unroll
    for (int g = 0; g < G; g++) {
        float w = w1[g * H + f];
        a0 += eas[0][g] * w;
        a1 += eas[1][g] * w;
        a2 += eas[2][g] * w;
    }
    a_s[0][f] = sspf(a0);
    a_s[1][f] = sspf(a1);
    a_s[2][f] = sspf(a2);
    __syncthreads();
    unsigned long long acc01 = 0ull;
    float accc = 0.f;
#pragma unroll 8
    for (int j = 0; j < H; j++) {
        float w = w2[j * H + f];
        fma2(acc01, pack2(a_s[0][j], a_s[1][j]), bcast2(w));
        accc = fmaf(a_s[2][j], w, accc);
    }
    float2 v01 = unpack2(acc01);
    float b2v = b2[f];
    float v0 = v01.x + b2v, v1 = v01.y + b2v, v2 = accc + b2v;
    float d0 = b0 * (CUTOFF_F / NBINS);
    float d1 = (b0 + 1) * (CUTOFF_F / NBINS);
    float d2 = (b0 + 2) * (CUTOFF_F / NBINS);
    v0 *= 0.5f * (cosf(d0 * (PI_F / CUTOFF_F)) + 1.f);
    v1 *= 0.5f * (cosf(d1 * (PI_F / CUTOFF_F)) + 1.f);
    v2 *= 0.5f * (cosf(d2 * (PI_F / CUTOFF_F)) + 1.f);
    g_tab2[b0 * H + f]       = __floats2half2_rn(v0, v1);
    if (b0 + 1 < NBINS)
        g_tab2[(b0 + 1) * H + f] = __floats2half2_rn(v1, v2);
}

// ======================= HMMA node GEMMs =======================
// Block: 256 threads = 8 warps (2 m-groups x 4 n-groups); tile 32 rows x 128 cols.
#define APAD 136

// stage fp32 A[32][128] -> smem fp16 (rows r0..r0+31, zero padded past M)
__device__ __forceinline__ void stage_A(const float* __restrict__ A, __half (*As)[APAD],
                                        int r0, int M, int tid) {
#pragma unroll
    for (int rep = 0; rep < 4; rep++) {
        int fl = tid + rep * 256;
        int row = fl >> 5, f4 = fl & 31;
        float4 v = (r0 + row < M) ? *(const float4*)&A[(size_t)(r0 + row) * H + f4 * 4]
                                  : make_float4(0.f, 0.f, 0.f, 0.f);
        __half2 h0 = __floats2half2_rn(v.x, v.y);
        __half2 h1 = __floats2half2_rn(v.z, v.w);
        __half2* p = (__half2*)&As[row][f4 * 4];
        p[0] = h0; p[1] = h1;
    }
}

// stage fp16 Wt[128][128] (n-major) -> smem
__device__ __forceinline__ void stage_W(const __half* __restrict__ Wt, __half (*Ws)[APAD], int tid) {
#pragma unroll
    for (int rep = 0; rep < 8; rep++) {
        int w = tid + rep * 256;
        int n = w >> 4, kg = w & 15;
        *(uint4*)&Ws[n][kg * 8] = *(const uint4*)&Wt[n * H + kg * 8];
    }
}

// mma over full k=128: acc[nt][4] for 4 n-tiles of this warp
__device__ __forceinline__ void hmma_block(const __half (*As)[APAD], const __half (*Ws)[APAD],
                                           float (&acc)[4][4], int warp_m, int warp_n,
                                           int tm, int tk) {
#pragma unroll
    for (int kc = 0; kc < 8; kc++) {
        int k0 = kc * 16;
        unsigned a0 = *(const unsigned*)&As[warp_m * 16 + tm][k0 + tk];
        unsigned a1 = *(const unsigned*)&As[warp_m * 16 + tm + 8][k0 + tk];
        unsigned a2 = *(const unsigned*)&As[warp_m * 16 + tm][k0 + 8 + tk];
        unsigned a3 = *(const unsigned*)&As[warp_m * 16 + tm + 8][k0 + 8 + tk];
#pragma unroll
        for (int nt = 0; nt < 4; nt++) {
            int n0 = warp_n * 32 + nt * 8;
            unsigned b0 = *(const unsigned*)&Ws[n0 + tm][k0 + tk];
            unsigned b1 = *(const unsigned*)&Ws[n0 + tm][k0 + 8 + tk];
            hmma16816(acc[nt][0], acc[nt][1], acc[nt][2], acc[nt][3], a0, a1, a2, a3, b0, b1);
        }
    }
}

// xf(fp16) = h @ W  (no bias)
__global__ void __launch_bounds__(256) gemm_xf(const float* __restrict__ A,
                                               const __half* __restrict__ Wt,
                                               __half* __restrict__ out, int M) {
    __shared__ __half As[32][APAD];
    __shared__ __half Ws[128][APAD];
    int tid = threadIdx.x;
    int warp = tid >> 5, lane = tid & 31;
    int warp_m = warp >> 2, warp_n = warp & 3;
    int tm = lane >> 2, tk = (lane & 3) * 2;
    int r0 = blockIdx.x * 32;
    stage_A(A, As, r0, M, tid);
    stage_W(Wt, Ws, tid);
    __syncthreads();
    float acc[4][4];
#pragma unroll
    for (int nt = 0; nt < 4; nt++)
#pragma unroll
        for (int i = 0; i < 4; i++) acc[nt][i] = 0.f;
    hmma_block(As, Ws, acc, warp_m, warp_n, tm, tk);
    int row1 = r0 + warp_m * 16 + tm;
    int row2 = row1 + 8;
#pragma unroll
    for (int nt = 0; nt < 4; nt++) {
        int col = warp_n * 32 + nt * 8 + tk;
        if (row1 < M) *(__half2*)&out[(size_t)row1 * H + col] = __floats2half2_rn(acc[nt][0], acc[nt][1]);
        if (row2 < M) *(__half2*)&out[(size_t)row2 * H + col] = __floats2half2_rn(acc[nt][2], acc[nt][3]);
    }
}

// h += ssp(agg @ W2 + b2) @ W3 + b3
__global__ void __launch_bounds__(256) gemm_dualH(const float* __restrict__ A,
                                                  const __half* __restrict__ W2t,
                                                  const float* __restrict__ b2,
                                                  const __half* __restrict__ W3t,
                                                  const float* __restrict__ b3,
                                                  float* __restrict__ out, int M) {
    __shared__ __half As[32][APAD];
    __shared__ __half Ws[128][APAD];
    int tid = threadIdx.x;
    int warp = tid >> 5, lane = tid & 31;
    int warp_m = warp >> 2, warp_n = warp & 3;
    int tm = lane >> 2, tk = (lane & 3) * 2;
    int r0 = blockIdx.x * 32;
    stage_A(A, As, r0, M, tid);
    stage_W(W2t, Ws, tid);
    __syncthreads();
    float acc[4][4];
#pragma unroll
    for (int nt = 0; nt < 4; nt++)
#pragma unroll
        for (int i = 0; i < 4; i++) acc[nt][i] = 0.f;
    hmma_block(As, Ws, acc, warp_m, warp_n, tm, tk);
    __syncthreads();   // all warps done reading As/Ws
    // epilogue 1: t = ssp(acc + b2)  -> As (fp16), and reload Ws = W3t
    {
        int lr1 = warp_m * 16 + tm;
        int lr2 = lr1 + 8;
#pragma unroll
        for (int nt = 0; nt < 4; nt++) {
            int col = warp_n * 32 + nt * 8 + tk;
            float2 bb = *(const float2*)&b2[col];
            *(__half2*)&As[lr1][col] = __floats2half2_rn(sspf(acc[nt][0] + bb.x), sspf(acc[nt][1] + bb.y));
            *(__half2*)&As[lr2][col] = __floats2half2_rn(sspf(acc[nt][2] + bb.x), sspf(acc[nt][3] + bb.y));
            acc[nt][0] = acc[nt][1] = acc[nt][2] = acc[nt][3] = 0.f;
        }
    }
    stage_W(W3t, Ws, tid);
    __syncthreads();
    hmma_block(As, Ws, acc, warp_m, warp_n, tm, tk);
    int row1 = r0 + warp_m * 16 + tm;
    int row2 = row1 + 8;
#pragma unroll
    for (int nt = 0; nt < 4; nt++) {
        int col = warp_n * 32 + nt * 8 + tk;
        float2 bb = *(const float2*)&b3[col];
        if (row1 < M) {
            float2* p = (float2*)&out[(size_t)row1 * H + col];
            float2 o = *p;
            o.x += acc[nt][0] + bb.x; o.y += acc[nt][1] + bb.y;
            *p = o;
        }
        if (row2 < M) {
            float2* p = (float2*)&out[(size_t)row2 * H + col];
            float2 o = *p;
            o.x += acc[nt][2] + bb.x; o.y += acc[nt][3] + bb.y;
            *p = o;
        }
    }
}

// ======================= Edge gather (warp per dst node, packed table) =======================
__global__ void edge_gather(int N) {
    int warp = (blockIdx.x * blockDim.x + threadIdx.x) >> 5;
    int lane = threadIdx.x & 31;
    if (warp >= N) return;
    int beg = g_rowptr[warp], end = g_rowptr[warp + 1];
    float a0 = 0.f, a1 = 0.f, a2 = 0.f, a3 = 0.f;
#pragma unroll 4
    for (int i = beg; i < end; i++) {
        int2 sd = g_csr[i];
        float d = __int_as_float(sd.y);
        float u = d * ((float)NBINS / CUTOFF_F);
        int i0 = min(max((int)u, 0), NBINS - 1);
        float fr = u - (float)i0;
        uint4 tp = *(const uint4*)&g_tab2[(size_t)i0 * H + lane * 4];
        uint2 xq = *(const uint2*)&g_xfh[(size_t)sd.x * H + lane * 4];
        float2 p0 = __half22float2(*(__half2*)&tp.x);
        float2 p1 = __half22float2(*(__half2*)&tp.y);
        float2 p2 = __half22float2(*(__half2*)&tp.z);
        float2 p3 = __half22float2(*(__half2*)&tp.w);
        float2 xa = __half22float2(*(__half2*)&xq.x);
        float2 xb = __half22float2(*(__half2*)&xq.y);
        a0 += xa.x * fmaf(fr, p0.y - p0.x, p0.x);
        a1 += xa.y * fmaf(fr, p1.y - p1.x, p1.x);
        a2 += xb.x * fmaf(fr, p2.y - p2.x, p2.x);
        a3 += xb.y * fmaf(fr, p3.y - p3.x, p3.x);
    }
    *(float4*)&g_agg[(size_t)warp * H + lane * 4] = make_float4(a0, a1, a2, a3);
}

// ======================= Readout =======================
__global__ void __launch_bounds__(256) readout_gemm(
    const float* __restrict__ A, const float* __restrict__ W,
    const float* __restrict__ bias, int M)
{
    constexpr int NCOL = 64;
    constexpr int CT = NCOL / 4;
    constexpr int ROWS = (256 / CT) * 4;
    __shared__ float As[ROWS][33];
    __shared__ float Ws[32][NCOL];
    __shared__ float csum[NCOL];
    int tid = threadIdx.x;
    int tx = tid % CT, ty = tid / CT;
    int r0 = blockIdx.x * ROWS;
    if (tid < NCOL) csum[tid] = 0.f;
    unsigned long long a01[4] = {0,0,0,0}, a23[4] = {0,0,0,0};
    for (int k0 = 0; k0 < 128; k0 += 32) {
        __syncthreads();
        for (int i = tid; i < ROWS * 32; i += 256) {
            int r = i >> 5, kk = i & 31;
            int row = r0 + r;
            As[r][kk] = (row < M) ? A[(size_t)row * 128 + k0 + kk] : 0.f;
        }
        for (int i = tid; i < 32 * NCOL; i += 256) {
            int kk = i / NCOL, c = i % NCOL;
            Ws[kk][c] = W[(size_t)(k0 + kk) * NCOL + c];
        }
        __syncthreads();
#pragma unroll
        for (int kk = 0; kk < 32; kk++) {
            ulonglong2 wv = *(const ulonglong2*)&Ws[kk][tx * 4];
#pragma unroll
            for (int i = 0; i < 4; i++) {
                unsigned long long a2 = bcast2(As[ty * 4 + i][kk]);
                fma2(a01[i], a2, wv.x);
                fma2(a23[i], a2, wv.y);
            }
        }
    }
    float4 bvq = *(const float4*)&bias[tx * 4];
#pragma unroll
    for (int i = 0; i < 4; i++) {
        int row = r0 + ty * 4 + i;
        if (row >= M) break;
        float2 p0 = unpack2(a01[i]);
        float2 p1 = unpack2(a23[i]);
        atomicAdd(&csum[tx * 4 + 0], sspf(p0.x + bvq.x));
        atomicAdd(&csum[tx * 4 + 1], sspf(p0.y + bvq.y));
        atomicAdd(&csum[tx * 4 + 2], sspf(p1.x + bvq.z));
        atomicAdd(&csum[tx * 4 + 3], sspf(p1.y + bvq.w));
    }
    __syncthreads();
    if (tid < NCOL) atomicAdd(&g_acc[tid], csum[tid]);
}

__global__ void readout_final(const float* __restrict__ o2w, const float* __restrict__ o2b,
                              const float* __restrict__ rw, const float* __restrict__ rb,
                              float* __restrict__ out, int N) {
    __shared__ float v[64];
    int t = threadIdx.x;
    float a = (float)N * o2b[t];
#pragma unroll 8
    for (int j = 0; j < 64; j++) a += g_acc[j] * o2w[j * 64 + t];
    v[t] = a;
    __syncthreads();
    if (t < 12) {
        float r = rb[t];
#pragma unroll
        for (int j = 0; j < 64; j++) r += v[j] * rw[j * 12 + t];
        out[t] = r;
    }
}

extern "C" void kernel_launch(void* const* d_in, const int* in_sizes, int n_in,
                              void* d_out, int out_size) {
    const int*   x    = (const int*)d_in[0];
    const int*   ei   = (const int*)d_in[1];
    const float* dist = (const float*)d_in[2];
    const float* emb  = (const float*)d_in[3];
    const float* mw1  = (const float*)d_in[4];
    const float* mb1  = (const float*)d_in[5];
    const float* mw2  = (const float*)d_in[6];
    const float* mb2  = (const float*)d_in[7];
    const float* l1w  = (const float*)d_in[8];
    const float* l2w  = (const float*)d_in[9];
    const float* l2b  = (const float*)d_in[10];
    const float* lw   = (const float*)d_in[11];
    const float* lb   = (const float*)d_in[12];
    const float* o1w  = (const float*)d_in[13];
    const float* o1b  = (const float*)d_in[14];
    const float* o2w  = (const float*)d_in[15];
    const float* o2b  = (const float*)d_in[16];
    const float* rw   = (const float*)d_in[17];
    const float* rb   = (const float*)d_in[18];

    int N = in_sizes[0];
    int E = in_sizes[2];
    int L = in_sizes[4] / (G * H);

    float *pacc;
    int *prow;
    cudaGetSymbolAddress((void**)&pacc, g_acc);
    cudaGetSymbolAddress((void**)&prow, g_rowptr);
    float *ph, *pagg;
    __half *pxfh, *pw1t, *pw2t, *pw3t;
    cudaGetSymbolAddress((void**)&ph, g_h);
    cudaGetSymbolAddress((void**)&pxfh, g_xfh);
    cudaGetSymbolAddress((void**)&pagg, g_agg);
    cudaGetSymbolAddress((void**)&pw1t, g_w1t);
    cudaGetSymbolAddress((void**)&pw2t, g_w2t);
    cudaGetSymbolAddress((void**)&pw3t, g_w3t);

    const int* esrc = ei;
    const int* edst = ei + E;

    int nbN = (N + 31) / 32;
    int nbE = (N + 7) / 8;
    int nbT = NBINS / 2;

    // launch order arranged so profiled launch #5 (ncu -s 5 -c 1) = gemm_xf
    convert_weights<<<256, 256>>>(l1w, l2w, lw, L);                       // 0
    embed_kernel<<<N, 128>>>(x, emb, N);                                  // 1
    cudaMemsetAsync(prow, 0, (N + 1) * sizeof(int));                      // 2
    hist_kernel<<<(E + 255) / 256, 256>>>(edst, E);                       // 3
    scan_kernel<<<1, 1024>>>(N + 1);                                      // 4 (writes cursor too)
    gemm_xf<<<nbN, 256>>>(ph, pw1t, pxfh, N);                             // 5  <- profiled
    scatter_kernel<<<(E + 255) / 256, 256>>>(esrc, edst, dist, E);        // 6
    table_fused<<<nbT, 128>>>(mw1, mb1, mw2, mb2);                        // 7
    edge_gather<<<nbE, 256>>>(N);                                         // 8
    gemm_dualH<<<nbN, 256>>>(pagg, pw2t, l2b, pw3t, lb, ph, N);           // 9

    for (int l = 1; l < L; l++) {
        table_fused<<<nbT, 128>>>(mw1 + (size_t)l * G * H, mb1 + (size_t)l * H,
                                  mw2 + (size_t)l * H * H, mb2 + (size_t)l * H);
        gemm_xf<<<nbN, 256>>>(ph, pw1t + (size_t)l * H * H, pxfh, N);
        edge_gather<<<nbE, 256>>>(N);
        gemm_dualH<<<nbN, 256>>>(pagg, pw2t + (size_t)l * H * H, l2b + (size_t)l * H,
                                 pw3t + (size_t)l * H * H, lb + (size_t)l * H, ph, N);
    }

    cudaMemsetAsync(pacc, 0, 64 * sizeof(float));
    readout_gemm<<<(N + 63) / 64, 256>>>(ph, o1w, o1b, N);
    readout_final<<<1, 64>>>(o2w, o2b, rw, rb, (float*)d_out, N);
}

// round 8
// speedup vs baseline: 1.9474x; 1.0653x over previous
#include <cuda_runtime.h>
#include <cuda_fp16.h>
#include <math.h>

#define H 128
#define G 50
#define NBINS 1024
#define CUTOFF_F 10.0f
#define NMAX 10000
#define EMAX 320000
#define LMAX 6
#define PI_F 3.14159265358979323846f

__device__ __align__(16) float  g_h[NMAX * H];
__device__ __align__(16) __half g_xfh[NMAX * H];
__device__ __align__(16) float  g_agg[NMAX * H];
__device__ __align__(16) __half2 g_tab2[LMAX * NBINS * H];  // [l][b][f] = (W[b][f], W[b+1][f])
__device__ float g_acc[64];
__device__ int  g_rowptr[NMAX + 1];
__device__ int  g_cursor[NMAX];
__device__ __align__(16) int2 g_csr[EMAX];
__device__ __align__(16) __half g_w1t[LMAX * H * H];
__device__ __align__(16) __half g_w2t[LMAX * H * H];
__device__ __align__(16) __half g_w3t[LMAX * H * H];

__device__ __forceinline__ float sspf(float x) {
    return fmaxf(x, 0.f) + log1pf(expf(-fabsf(x))) - 0.69314718055994530942f;
}

// ---- f32x2 packed-FMA helpers (table build / readout) ----
__device__ __forceinline__ void fma2(unsigned long long& d, unsigned long long a, unsigned long long b) {
    asm("fma.rn.f32x2 %0, %1, %2, %0;" : "+l"(d) : "l"(a), "l"(b));
}
__device__ __forceinline__ unsigned long long bcast2(float a) {
    unsigned long long r; asm("mov.b64 %0, {%1, %1};" : "=l"(r) : "f"(a)); return r;
}
__device__ __forceinline__ unsigned long long pack2(float a, float b) {
    unsigned long long r; asm("mov.b64 %0, {%1, %2};" : "=l"(r) : "f"(a), "f"(b)); return r;
}
__device__ __forceinline__ float2 unpack2(unsigned long long v) {
    float2 f; asm("mov.b64 {%0, %1}, %2;" : "=f"(f.x), "=f"(f.y) : "l"(v)); return f;
}

// ---- HMMA m16n8k16 fp16 -> fp32 ----
__device__ __forceinline__ void hmma16816(float& c0, float& c1, float& c2, float& c3,
                                          unsigned a0, unsigned a1, unsigned a2, unsigned a3,
                                          unsigned b0, unsigned b1) {
    asm volatile(
        "mma.sync.aligned.m16n8k16.row.col.f32.f16.f16.f32 "
        "{%0,%1,%2,%3}, {%4,%5,%6,%7}, {%8,%9}, {%0,%1,%2,%3};"
        : "+f"(c0), "+f"(c1), "+f"(c2), "+f"(c3)
        : "r"(a0), "r"(a1), "r"(a2), "r"(a3), "r"(b0), "r"(b1));
}

__global__ void convert_weights(const float* __restrict__ w1, const float* __restrict__ w2,
                                const float* __restrict__ w3, int L) {
    int total = L * H * H;
    for (int idx = blockIdx.x * blockDim.x + threadIdx.x; idx < total; idx += gridDim.x * blockDim.x) {
        int l = idx >> 14;
        int r = idx & 16383;
        int k = r >> 7, n = r & 127;
        int o = (l << 14) + (n << 7) + k;
        g_w1t[o] = __float2half(w1[idx]);
        g_w2t[o] = __float2half(w2[idx]);
        g_w3t[o] = __float2half(w3[idx]);
    }
}

__global__ void embed_kernel(const int* __restrict__ x, const float* __restrict__ emb, int N) {
    int n = blockIdx.x;
    if (n < N) g_h[n * H + threadIdx.x] = emb[x[n] * H + threadIdx.x];
}

// ======================= CSR build =======================
__global__ void hist_kernel(const int* __restrict__ dst, int E) {
    int e = blockIdx.x * blockDim.x + threadIdx.x;
    if (e < E) atomicAdd(&g_rowptr[dst[e] + 1], 1);
}

// single-block inclusive scan via smem staging (n <= 10240)
__global__ void __launch_bounds__(1024) scan_kernel(int n) {
    __shared__ int buf[10240];
    __shared__ int wsum[32];
    int t = threadIdx.x;
    const int C = 10;
    for (int i = t; i < 10240; i += 1024) buf[i] = (i < n) ? g_rowptr[i] : 0;
    __syncthreads();
    int base = t * C;
    int s = 0;
#pragma unroll
    for (int i = 0; i < C; i++) s += buf[base + i];
    int lane = t & 31, w = t >> 5;
    int v = s;
#pragma unroll
    for (int off = 1; off < 32; off <<= 1) {
        int u = __shfl_up_sync(0xffffffffu, v, off);
        if (lane >= off) v += u;
    }
    if (lane == 31) wsum[w] = v;
    __syncthreads();
    if (w == 0) {
        int xv = wsum[lane];
#pragma unroll
        for (int off = 1; off < 32; off <<= 1) {
            int u = __shfl_up_sync(0xffffffffu, xv, off);
            if (lane >= off) xv += u;
        }
        wsum[lane] = xv;
    }
    __syncthreads();
    int run = v - s + (w > 0 ? wsum[w - 1] : 0);
#pragma unroll
    for (int i = 0; i < C; i++) { run += buf[base + i]; buf[base + i] = run; }
    __syncthreads();
    for (int i = t; i < n; i += 1024) {
        int val = buf[i];
        g_rowptr[i] = val;
        if (i < n - 1) g_cursor[i] = val;
    }
}

__global__ void scatter_kernel(const int* __restrict__ src, const int* __restrict__ dst,
                               const float* __restrict__ dist, int E) {
    int e = blockIdx.x * blockDim.x + threadIdx.x;
    if (e < E) {
        int p = atomicAdd(&g_cursor[dst[e]], 1);
        g_csr[p] = make_int2(src[e], __float_as_int(dist[e]));
    }
}

// ======================= Filter tables for ALL layers in one launch ====
__global__ void __launch_bounds__(128) table_all(
    const float* __restrict__ mw1, const float* __restrict__ mb1,
    const float* __restrict__ mw2, const float* __restrict__ mb2)
{
    __shared__ float a_s[3][H];
    __shared__ float eas[3][G];
    int f = threadIdx.x;
    int b0 = blockIdx.x * 2;
    int l = blockIdx.y;
    const float* w1 = mw1 + (size_t)l * G * H;
    const float* b1 = mb1 + (size_t)l * H;
    const float* w2 = mw2 + (size_t)l * H * H;
    const float* b2 = mb2 + (size_t)l * H;
    __half2* tab = g_tab2 + (size_t)l * NBINS * H;
    const float spacing = CUTOFF_F / (G - 1);
    const float coeff = -0.5f / (spacing * spacing);
    for (int i = f; i < 3 * G; i += 128) {
        int bi = i / G, g = i - bi * G;
        float d = (b0 + bi) * (CUTOFF_F / NBINS);
        float dd = d - g * spacing;
        eas[bi][g] = expf(coeff * dd * dd);
    }
    __syncthreads();
    float bv = b1[f];
    float a0 = bv, a1 = bv, a2 = bv;
#pragma unroll
    for (int g = 0; g < G; g++) {
        float w = w1[g * H + f];
        a0 += eas[0][g] * w;
        a1 += eas[1][g] * w;
        a2 += eas[2][g] * w;
    }
    a_s[0][f] = sspf(a0);
    a_s[1][f] = sspf(a1);
    a_s[2][f] = sspf(a2);
    __syncthreads();
    unsigned long long acc01 = 0ull;
    float accc = 0.f;
#pragma unroll 8
    for (int j = 0; j < H; j++) {
        float w = w2[j * H + f];
        fma2(acc01, pack2(a_s[0][j], a_s[1][j]), bcast2(w));
        accc = fmaf(a_s[2][j], w, accc);
    }
    float2 v01 = unpack2(acc01);
    float b2v = b2[f];
    float v0 = v01.x + b2v, v1 = v01.y + b2v, v2 = accc + b2v;
    float d0 = b0 * (CUTOFF_F / NBINS);
    float d1 = (b0 + 1) * (CUTOFF_F / NBINS);
    float d2 = (b0 + 2) * (CUTOFF_F / NBINS);
    v0 *= 0.5f * (cosf(d0 * (PI_F / CUTOFF_F)) + 1.f);
    v1 *= 0.5f * (cosf(d1 * (PI_F / CUTOFF_F)) + 1.f);
    v2 *= 0.5f * (cosf(d2 * (PI_F / CUTOFF_F)) + 1.f);
    tab[b0 * H + f] = __floats2half2_rn(v0, v1);
    if (b0 + 1 < NBINS)
        tab[(b0 + 1) * H + f] = __floats2half2_rn(v1, v2);
}

// ======================= HMMA node GEMMs =======================
#define APAD 136

__device__ __forceinline__ void stage_A(const float* __restrict__ A, __half (*As)[APAD],
                                        int r0, int M, int tid) {
#pragma unroll
    for (int rep = 0; rep < 4; rep++) {
        int fl = tid + rep * 256;
        int row = fl >> 5, f4 = fl & 31;
        float4 v = (r0 + row < M) ? *(const float4*)&A[(size_t)(r0 + row) * H + f4 * 4]
                                  : make_float4(0.f, 0.f, 0.f, 0.f);
        __half2 h0 = __floats2half2_rn(v.x, v.y);
        __half2 h1 = __floats2half2_rn(v.z, v.w);
        __half2* p = (__half2*)&As[row][f4 * 4];
        p[0] = h0; p[1] = h1;
    }
}

__device__ __forceinline__ void stage_W(const __half* __restrict__ Wt, __half (*Ws)[APAD], int tid) {
#pragma unroll
    for (int rep = 0; rep < 8; rep++) {
        int w = tid + rep * 256;
        int n = w >> 4, kg = w & 15;
        *(uint4*)&Ws[n][kg * 8] = *(const uint4*)&Wt[n * H + kg * 8];
    }
}

__device__ __forceinline__ void hmma_block(const __half (*As)[APAD], const __half (*Ws)[APAD],
                                           float (&acc)[4][4], int warp_m, int warp_n,
                                           int tm, int tk) {
#pragma unroll
    for (int kc = 0; kc < 8; kc++) {
        int k0 = kc * 16;
        unsigned a0 = *(const unsigned*)&As[warp_m * 16 + tm][k0 + tk];
        unsigned a1 = *(const unsigned*)&As[warp_m * 16 + tm + 8][k0 + tk];
        unsigned a2 = *(const unsigned*)&As[warp_m * 16 + tm][k0 + 8 + tk];
        unsigned a3 = *(const unsigned*)&As[warp_m * 16 + tm + 8][k0 + 8 + tk];
#pragma unroll
        for (int nt = 0; nt < 4; nt++) {
            int n0 = warp_n * 32 + nt * 8;
            unsigned b0 = *(const unsigned*)&Ws[n0 + tm][k0 + tk];
            unsigned b1 = *(const unsigned*)&Ws[n0 + tm][k0 + 8 + tk];
            hmma16816(acc[nt][0], acc[nt][1], acc[nt][2], acc[nt][3], a0, a1, a2, a3, b0, b1);
        }
    }
}

// xf(fp16) = h @ W  (layer 0 only)
__global__ void __launch_bounds__(256) gemm_xf(const float* __restrict__ A,
                                               const __half* __restrict__ Wt,
                                               __half* __restrict__ out, int M) {
    __shared__ __half As[32][APAD];
    __shared__ __half Ws[128][APAD];
    int tid = threadIdx.x;
    int warp = tid >> 5, lane = tid & 31;
    int warp_m = warp >> 2, warp_n = warp & 3;
    int tm = lane >> 2, tk = (lane & 3) * 2;
    int r0 = blockIdx.x * 32;
    stage_A(A, As, r0, M, tid);
    stage_W(Wt, Ws, tid);
    __syncthreads();
    float acc[4][4];
#pragma unroll
    for (int nt = 0; nt < 4; nt++)
#pragma unroll
        for (int i = 0; i < 4; i++) acc[nt][i] = 0.f;
    hmma_block(As, Ws, acc, warp_m, warp_n, tm, tk);
    int row1 = r0 + warp_m * 16 + tm;
    int row2 = row1 + 8;
#pragma unroll
    for (int nt = 0; nt < 4; nt++) {
        int col = warp_n * 32 + nt * 8 + tk;
        if (row1 < M) *(__half2*)&out[(size_t)row1 * H + col] = __floats2half2_rn(acc[nt][0], acc[nt][1]);
        if (row2 < M) *(__half2*)&out[(size_t)row2 * H + col] = __floats2half2_rn(acc[nt][2], acc[nt][3]);
    }
}

// h += ssp(agg @ W2 + b2) @ W3 + b3;  then (optional) xf_next = h_new @ W1n
__global__ void __launch_bounds__(256) gemm_dualX(const float* __restrict__ A,
                                                  const __half* __restrict__ W2t,
                                                  const float* __restrict__ b2,
                                                  const __half* __restrict__ W3t,
                                                  const float* __restrict__ b3,
                                                  float* __restrict__ hio,
                                                  const __half* __restrict__ W1n,
                                                  __half* __restrict__ xf, int M) {
    __shared__ __half As[32][APAD];
    __shared__ __half Ws[128][APAD];
    int tid = threadIdx.x;
    int warp = tid >> 5, lane = tid & 31;
    int warp_m = warp >> 2, warp_n = warp & 3;
    int tm = lane >> 2, tk = (lane & 3) * 2;
    int r0 = blockIdx.x * 32;
    int lr1 = warp_m * 16 + tm, lr2 = lr1 + 8;
    int row1 = r0 + lr1, row2 = r0 + lr2;

    stage_A(A, As, r0, M, tid);
    stage_W(W2t, Ws, tid);
    __syncthreads();
    float acc[4][4];
#pragma unroll
    for (int nt = 0; nt < 4; nt++)
#pragma unroll
        for (int i = 0; i < 4; i++) acc[nt][i] = 0.f;
    hmma_block(As, Ws, acc, warp_m, warp_n, tm, tk);
    __syncthreads();
    // epi 1: t = ssp(acc + b2) -> As ; reload Ws = W3t
#pragma unroll
    for (int nt = 0; nt < 4; nt++) {
        int col = warp_n * 32 + nt * 8 + tk;
        float2 bb = *(const float2*)&b2[col];
        *(__half2*)&As[lr1][col] = __floats2half2_rn(sspf(acc[nt][0] + bb.x), sspf(acc[nt][1] + bb.y));
        *(__half2*)&As[lr2][col] = __floats2half2_rn(sspf(acc[nt][2] + bb.x), sspf(acc[nt][3] + bb.y));
        acc[nt][0] = acc[nt][1] = acc[nt][2] = acc[nt][3] = 0.f;
    }
    stage_W(W3t, Ws, tid);
    __syncthreads();
    hmma_block(As, Ws, acc, warp_m, warp_n, tm, tk);
    __syncthreads();
    // epi 2: h_new = h_old + acc + b3 -> global fp32 AND As fp16
#pragma unroll
    for (int nt = 0; nt < 4; nt++) {
        int col = warp_n * 32 + nt * 8 + tk;
        float2 bb = *(const float2*)&b3[col];
        float2 o1 = make_float2(0.f, 0.f), o2 = make_float2(0.f, 0.f);
        if (row1 < M) o1 = *(const float2*)&hio[(size_t)row1 * H + col];
        if (row2 < M) o2 = *(const float2*)&hio[(size_t)row2 * H + col];
        o1.x += acc[nt][0] + bb.x; o1.y += acc[nt][1] + bb.y;
        o2.x += acc[nt][2] + bb.x; o2.y += acc[nt][3] + bb.y;
        if (row1 < M) *(float2*)&hio[(size_t)row1 * H + col] = o1;
        if (row2 < M) *(float2*)&hio[(size_t)row2 * H + col] = o2;
        *(__half2*)&As[lr1][col] = __floats2half2_rn(o1.x, o1.y);
        *(__half2*)&As[lr2][col] = __floats2half2_rn(o2.x, o2.y);
        acc[nt][0] = acc[nt][1] = acc[nt][2] = acc[nt][3] = 0.f;
    }
    if (W1n) {
        stage_W(W1n, Ws, tid);
        __syncthreads();
        hmma_block(As, Ws, acc, warp_m, warp_n, tm, tk);
#pragma unroll
        for (int nt = 0; nt < 4; nt++) {
            int col = warp_n * 32 + nt * 8 + tk;
            if (row1 < M) *(__half2*)&xf[(size_t)row1 * H + col] = __floats2half2_rn(acc[nt][0], acc[nt][1]);
            if (row2 < M) *(__half2*)&xf[(size_t)row2 * H + col] = __floats2half2_rn(acc[nt][2], acc[nt][3]);
        }
    }
}

// ======================= Edge gather =======================
__global__ void edge_gather(const __half2* __restrict__ tab, int N) {
    int warp = (blockIdx.x * blockDim.x + threadIdx.x) >> 5;
    int lane = threadIdx.x & 31;
    if (warp >= N) return;
    int beg = g_rowptr[warp], end = g_rowptr[warp + 1];
    float a0 = 0.f, a1 = 0.f, a2 = 0.f, a3 = 0.f;
#pragma unroll 4
    for (int i = beg; i < end; i++) {
        int2 sd = g_csr[i];
        float d = __int_as_float(sd.y);
        float u = d * ((float)NBINS / CUTOFF_F);
        int i0 = min(max((int)u, 0), NBINS - 1);
        float fr = u - (float)i0;
        uint4 tp = *(const uint4*)&tab[(size_t)i0 * H + lane * 4];
        uint2 xq = *(const uint2*)&g_xfh[(size_t)sd.x * H + lane * 4];
        float2 p0 = __half22float2(*(__half2*)&tp.x);
        float2 p1 = __half22float2(*(__half2*)&tp.y);
        float2 p2 = __half22float2(*(__half2*)&tp.z);
        float2 p3 = __half22float2(*(__half2*)&tp.w);
        float2 xa = __half22float2(*(__half2*)&xq.x);
        float2 xb = __half22float2(*(__half2*)&xq.y);
        a0 += xa.x * fmaf(fr, p0.y - p0.x, p0.x);
        a1 += xa.y * fmaf(fr, p1.y - p1.x, p1.x);
        a2 += xb.x * fmaf(fr, p2.y - p2.x, p2.x);
        a3 += xb.y * fmaf(fr, p3.y - p3.x, p3.x);
    }
    *(float4*)&g_agg[(size_t)warp * H + lane * 4] = make_float4(a0, a1, a2, a3);
}

// ======================= Readout =======================
__global__ void __launch_bounds__(256) readout_gemm(
    const float* __restrict__ A, const float* __restrict__ W,
    const float* __restrict__ bias, int M)
{
    constexpr int NCOL = 64;
    constexpr int CT = NCOL / 4;
    constexpr int ROWS = (256 / CT) * 4;
    __shared__ float As[ROWS][33];
    __shared__ float Ws[32][NCOL];
    __shared__ float csum[NCOL];
    int tid = threadIdx.x;
    int tx = tid % CT, ty = tid / CT;
    int r0 = blockIdx.x * ROWS;
    if (tid < NCOL) csum[tid] = 0.f;
    unsigned long long a01[4] = {0,0,0,0}, a23[4] = {0,0,0,0};
    for (int k0 = 0; k0 < 128; k0 += 32) {
        __syncthreads();
        for (int i = tid; i < ROWS * 32; i += 256) {
            int r = i >> 5, kk = i & 31;
            int row = r0 + r;
            As[r][kk] = (row < M) ? A[(size_t)row * 128 + k0 + kk] : 0.f;
        }
        for (int i = tid; i < 32 * NCOL; i += 256) {
            int kk = i / NCOL, c = i % NCOL;
            Ws[kk][c] = W[(size_t)(k0 + kk) * NCOL + c];
        }
        __syncthreads();
#pragma unroll
        for (int kk = 0; kk < 32; kk++) {
            ulonglong2 wv = *(const ulonglong2*)&Ws[kk][tx * 4];
#pragma unroll
            for (int i = 0; i < 4; i++) {
                unsigned long long a2 = bcast2(As[ty * 4 + i][kk]);
                fma2(a01[i], a2, wv.x);
                fma2(a23[i], a2, wv.y);
            }
        }
    }
    float4 bvq = *(const float4*)&bias[tx * 4];
#pragma unroll
    for (int i = 0; i < 4; i++) {
        int row = r0 + ty * 4 + i;
        if (row >= M) break;
        float2 p0 = unpack2(a01[i]);
        float2 p1 = unpack2(a23[i]);
        atomicAdd(&csum[tx * 4 + 0], sspf(p0.x + bvq.x));
        atomicAdd(&csum[tx * 4 + 1], sspf(p0.y + bvq.y));
        atomicAdd(&csum[tx * 4 + 2], sspf(p1.x + bvq.z));
        atomicAdd(&csum[tx * 4 + 3], sspf(p1.y + bvq.w));
    }
    __syncthreads();
    if (tid < NCOL) atomicAdd(&g_acc[tid], csum[tid]);
}

__global__ void readout_final(const float* __restrict__ o2w, const float* __restrict__ o2b,
                              const float* __restrict__ rw, const float* __restrict__ rb,
                              float* __restrict__ out, int N) {
    __shared__ float v[64];
    int t = threadIdx.x;
    float a = (float)N * o2b[t];
#pragma unroll 8
    for (int j = 0; j < 64; j++) a += g_acc[j] * o2w[j * 64 + t];
    v[t] = a;
    __syncthreads();
    if (t < 12) {
        float r = rb[t];
#pragma unroll
        for (int j = 0; j < 64; j++) r += v[j] * rw[j * 12 + t];
        out[t] = r;
    }
}

extern "C" void kernel_launch(void* const* d_in, const int* in_sizes, int n_in,
                              void* d_out, int out_size) {
    const int*   x    = (const int*)d_in[0];
    const int*   ei   = (const int*)d_in[1];
    const float* dist = (const float*)d_in[2];
    const float* emb  = (const float*)d_in[3];
    const float* mw1  = (const float*)d_in[4];
    const float* mb1  = (const float*)d_in[5];
    const float* mw2  = (const float*)d_in[6];
    const float* mb2  = (const float*)d_in[7];
    const float* l1w  = (const float*)d_in[8];
    const float* l2w  = (const float*)d_in[9];
    const float* l2b  = (const float*)d_in[10];
    const float* lw   = (const float*)d_in[11];
    const float* lb   = (const float*)d_in[12];
    const float* o1w  = (const float*)d_in[13];
    const float* o1b  = (const float*)d_in[14];
    const float* o2w  = (const float*)d_in[15];
    const float* o2b  = (const float*)d_in[16];
    const float* rw   = (const float*)d_in[17];
    const float* rb   = (const float*)d_in[18];

    int N = in_sizes[0];
    int E = in_sizes[2];
    int L = in_sizes[4] / (G * H);

    float *pacc;
    int *prow;
    cudaGetSymbolAddress((void**)&pacc, g_acc);
    cudaGetSymbolAddress((void**)&prow, g_rowptr);
    float *ph, *pagg;
    __half *pxfh, *pw1t, *pw2t, *pw3t;
    __half2 *ptab;
    cudaGetSymbolAddress((void**)&ph, g_h);
    cudaGetSymbolAddress((void**)&pxfh, g_xfh);
    cudaGetSymbolAddress((void**)&pagg, g_agg);
    cudaGetSymbolAddress((void**)&pw1t, g_w1t);
    cudaGetSymbolAddress((void**)&pw2t, g_w2t);
    cudaGetSymbolAddress((void**)&pw3t, g_w3t);
    cudaGetSymbolAddress((void**)&ptab, g_tab2);

    const int* esrc = ei;
    const int* edst = ei + E;

    int nbN = (N + 31) / 32;
    int nbE = (N + 7) / 8;

    convert_weights<<<256, 256>>>(l1w, l2w, lw, L);                       // 1
    embed_kernel<<<N, 128>>>(x, emb, N);                                  // 2
    cudaMemsetAsync(prow, 0, (N + 1) * sizeof(int));                      // 3
    hist_kernel<<<(E + 255) / 256, 256>>>(edst, E);                       // 4
    gemm_xf<<<nbN, 256>>>(ph, pw1t, pxfh, N);                             // 5  <- profiled
    scan_kernel<<<1, 1024>>>(N + 1);                                      // 6
    scatter_kernel<<<(E + 255) / 256, 256>>>(esrc, edst, dist, E);        // 7
    dim3 tgrid(NBINS / 2, L);
    table_all<<<tgrid, 128>>>(mw1, mb1, mw2, mb2);                        // 8

    for (int l = 0; l < L; l++) {
        edge_gather<<<nbE, 256>>>(ptab + (size_t)l * NBINS * H, N);
        const __half* w1n = (l + 1 < L) ? pw1t + (size_t)(l + 1) * H * H : nullptr;
        gemm_dualX<<<nbN, 256>>>(pagg, pw2t + (size_t)l * H * H, l2b + (size_t)l * H,
                                 pw3t + (size_t)l * H * H, lb + (size_t)l * H,
                                 ph, w1n, pxfh, N);
    }

    cudaMemsetAsync(pacc, 0, 64 * sizeof(float));
    readout_gemm<<<(N + 63) / 64, 256>>>(ph, o1w, o1b, N);
    readout_final<<<1, 64>>>(o2w, o2b, rw, rb, (float*)d_out, N);
}

// round 9
// speedup vs baseline: 1.9926x; 1.0232x over previous
#include <cuda_runtime.h>
#include <cuda_fp16.h>
#include <math.h>

#define H 128
#define G 50
#define NBINS 1024
#define CUTOFF_F 10.0f
#define NMAX 10000
#define EMAX 320000
#define LMAX 6
#define PI_F 3.14159265358979323846f

__device__ __align__(16) float  g_h[NMAX * H];
__device__ __align__(16) __half g_xfh[NMAX * H];
__device__ __align__(16) __half g_aggh[NMAX * H];
__device__ __align__(16) __half2 g_tab2[LMAX * NBINS * H];
__device__ float g_acc[64];
__device__ int  g_rowptr[NMAX + 1];
__device__ int  g_rank[EMAX];
__device__ __align__(16) int2 g_csr[EMAX];
__device__ __align__(16) __half g_w1t[LMAX * H * H];
__device__ __align__(16) __half g_w2t[LMAX * H * H];
__device__ __align__(16) __half g_w3t[LMAX * H * H];
__device__ __align__(16) __half g_o1t[64 * H];

__device__ __forceinline__ float sspf(float x) {
    return fmaxf(x, 0.f) + log1pf(expf(-fabsf(x))) - 0.69314718055994530942f;
}

// ---- f32x2 helpers (table build) ----
__device__ __forceinline__ void fma2(unsigned long long& d, unsigned long long a, unsigned long long b) {
    asm("fma.rn.f32x2 %0, %1, %2, %0;" : "+l"(d) : "l"(a), "l"(b));
}
__device__ __forceinline__ unsigned long long bcast2(float a) {
    unsigned long long r; asm("mov.b64 %0, {%1, %1};" : "=l"(r) : "f"(a)); return r;
}
__device__ __forceinline__ unsigned long long pack2(float a, float b) {
    unsigned long long r; asm("mov.b64 %0, {%1, %2};" : "=l"(r) : "f"(a), "f"(b)); return r;
}
__device__ __forceinline__ float2 unpack2(unsigned long long v) {
    float2 f; asm("mov.b64 {%0, %1}, %2;" : "=f"(f.x), "=f"(f.y) : "l"(v)); return f;
}

// ---- HMMA m16n8k16 ----
__device__ __forceinline__ void hmma16816(float& c0, float& c1, float& c2, float& c3,
                                          unsigned a0, unsigned a1, unsigned a2, unsigned a3,
                                          unsigned b0, unsigned b1) {
    asm volatile(
        "mma.sync.aligned.m16n8k16.row.col.f32.f16.f16.f32 "
        "{%0,%1,%2,%3}, {%4,%5,%6,%7}, {%8,%9}, {%0,%1,%2,%3};"
        : "+f"(c0), "+f"(c1), "+f"(c2), "+f"(c3)
        : "r"(a0), "r"(a1), "r"(a2), "r"(a3), "r"(b0), "r"(b1));
}

__global__ void convert_weights(const float* __restrict__ w1, const float* __restrict__ w2,
                                const float* __restrict__ w3, const float* __restrict__ o1w, int L) {
    int total = L * H * H;
    for (int idx = blockIdx.x * blockDim.x + threadIdx.x; idx < total; idx += gridDim.x * blockDim.x) {
        int l = idx >> 14;
        int r = idx & 16383;
        int k = r >> 7, n = r & 127;
        int o = (l << 14) + (n << 7) + k;
        g_w1t[o] = __float2half(w1[idx]);
        g_w2t[o] = __float2half(w2[idx]);
        g_w3t[o] = __float2half(w3[idx]);
    }
    for (int idx = blockIdx.x * blockDim.x + threadIdx.x; idx < H * 64; idx += gridDim.x * blockDim.x) {
        int k = idx >> 6, n = idx & 63;
        g_o1t[n * H + k] = __float2half(o1w[idx]);
    }
}

__global__ void embed_kernel(const int* __restrict__ x, const float* __restrict__ emb, int N) {
    int n = blockIdx.x;
    if (n < N) g_h[n * H + threadIdx.x] = emb[x[n] * H + threadIdx.x];
}

// ======================= CSR build =======================
__global__ void hist_kernel(const int* __restrict__ dst, int E) {
    int e = blockIdx.x * blockDim.x + threadIdx.x;
    if (e < E) g_rank[e] = atomicAdd(&g_rowptr[dst[e] + 1], 1);
}

__global__ void __launch_bounds__(1024) scan_kernel(int n) {
    __shared__ int buf[10240];
    __shared__ int wsum[32];
    int t = threadIdx.x;
    const int C = 10;
    for (int i = t; i < 10240; i += 1024) buf[i] = (i < n) ? g_rowptr[i] : 0;
    __syncthreads();
    int base = t * C;
    int s = 0;
#pragma unroll
    for (int i = 0; i < C; i++) s += buf[base + i];
    int lane = t & 31, w = t >> 5;
    int v = s;
#pragma unroll
    for (int off = 1; off < 32; off <<= 1) {
        int u = __shfl_up_sync(0xffffffffu, v, off);
        if (lane >= off) v += u;
    }
    if (lane == 31) wsum[w] = v;
    __syncthreads();
    if (w == 0) {
        int xv = wsum[lane];
#pragma unroll
        for (int off = 1; off < 32; off <<= 1) {
            int u = __shfl_up_sync(0xffffffffu, xv, off);
            if (lane >= off) xv += u;
        }
        wsum[lane] = xv;
    }
    __syncthreads();
    int run = v - s + (w > 0 ? wsum[w - 1] : 0);
#pragma unroll
    for (int i = 0; i < C; i++) { run += buf[base + i]; buf[base + i] = run; }
    __syncthreads();
    for (int i = t; i < n; i += 1024) g_rowptr[i] = buf[i];
}

// atomic-free: pos = rowptr[dst] + precomputed rank
__global__ void scatter_kernel(const int* __restrict__ src, const int* __restrict__ dst,
                               const float* __restrict__ dist, int E) {
    int e = blockIdx.x * blockDim.x + threadIdx.x;
    if (e < E) {
        int p = g_rowptr[dst[e]] + g_rank[e];
        g_csr[p] = make_int2(src[e], __float_as_int(dist[e]));
    }
}

// ======================= Filter tables (all layers, one launch) ====
__global__ void __launch_bounds__(128) table_all(
    const float* __restrict__ mw1, const float* __restrict__ mb1,
    const float* __restrict__ mw2, const float* __restrict__ mb2)
{
    __shared__ float a_s[3][H];
    __shared__ float eas[3][G];
    int f = threadIdx.x;
    int b0 = blockIdx.x * 2;
    int l = blockIdx.y;
    const float* w1 = mw1 + (size_t)l * G * H;
    const float* b1 = mb1 + (size_t)l * H;
    const float* w2 = mw2 + (size_t)l * H * H;
    const float* b2 = mb2 + (size_t)l * H;
    __half2* tab = g_tab2 + (size_t)l * NBINS * H;
    const float spacing = CUTOFF_F / (G - 1);
    const float coeff = -0.5f / (spacing * spacing);
    for (int i = f; i < 3 * G; i += 128) {
        int bi = i / G, g = i - bi * G;
        float d = (b0 + bi) * (CUTOFF_F / NBINS);
        float dd = d - g * spacing;
        eas[bi][g] = expf(coeff * dd * dd);
    }
    __syncthreads();
    float bv = b1[f];
    float a0 = bv, a1 = bv, a2 = bv;
#pragma unroll
    for (int g = 0; g < G; g++) {
        float w = w1[g * H + f];
        a0 += eas[0][g] * w;
        a1 += eas[1][g] * w;
        a2 += eas[2][g] * w;
    }
    a_s[0][f] = sspf(a0);
    a_s[1][f] = sspf(a1);
    a_s[2][f] = sspf(a2);
    __syncthreads();
    unsigned long long acc01 = 0ull;
    float accc = 0.f;
#pragma unroll 8
    for (int j = 0; j < H; j++) {
        float w = w2[j * H + f];
        fma2(acc01, pack2(a_s[0][j], a_s[1][j]), bcast2(w));
        accc = fmaf(a_s[2][j], w, accc);
    }
    float2 v01 = unpack2(acc01);
    float b2v = b2[f];
    float v0 = v01.x + b2v, v1 = v01.y + b2v, v2 = accc + b2v;
    float d0 = b0 * (CUTOFF_F / NBINS);
    float d1 = (b0 + 1) * (CUTOFF_F / NBINS);
    float d2 = (b0 + 2) * (CUTOFF_F / NBINS);
    v0 *= 0.5f * (cosf(d0 * (PI_F / CUTOFF_F)) + 1.f);
    v1 *= 0.5f * (cosf(d1 * (PI_F / CUTOFF_F)) + 1.f);
    v2 *= 0.5f * (cosf(d2 * (PI_F / CUTOFF_F)) + 1.f);
    tab[b0 * H + f] = __floats2half2_rn(v0, v1);
    if (b0 + 1 < NBINS)
        tab[(b0 + 1) * H + f] = __floats2half2_rn(v1, v2);
}

// ======================= HMMA kernels (64-row tiles) =======================
#define APAD 136

// fp32 -> fp16 stage, 64 rows
__device__ __forceinline__ void stage_A64(const float* __restrict__ A, __half (*As)[APAD],
                                          int r0, int M, int tid) {
#pragma unroll
    for (int rep = 0; rep < 8; rep++) {
        int fl = tid + rep * 256;
        int row = fl >> 5, f4 = fl & 31;
        float4 v = (r0 + row < M) ? *(const float4*)&A[(size_t)(r0 + row) * H + f4 * 4]
                                  : make_float4(0.f, 0.f, 0.f, 0.f);
        __half2* p = (__half2*)&As[row][f4 * 4];
        p[0] = __floats2half2_rn(v.x, v.y);
        p[1] = __floats2half2_rn(v.z, v.w);
    }
}

// fp16 copy stage, 64 rows
__device__ __forceinline__ void stage_Ah64(const __half* __restrict__ A, __half (*As)[APAD],
                                           int r0, int M, int tid) {
#pragma unroll
    for (int rep = 0; rep < 4; rep++) {
        int fl = tid + rep * 256;
        int row = fl >> 4, u4 = fl & 15;
        uint4 v = (r0 + row < M) ? *(const uint4*)&A[(size_t)(r0 + row) * H + u4 * 8]
                                 : make_uint4(0u, 0u, 0u, 0u);
        *(uint4*)&As[row][u4 * 8] = v;
    }
}

__device__ __forceinline__ void stage_W(const __half* __restrict__ Wt, __half (*Ws)[APAD], int tid) {
#pragma unroll
    for (int rep = 0; rep < 8; rep++) {
        int w = tid + rep * 256;
        int n = w >> 4, kg = w & 15;
        *(uint4*)&Ws[n][kg * 8] = *(const uint4*)&Wt[n * H + kg * 8];
    }
}

__device__ __forceinline__ void stage_W64(const __half* __restrict__ Wt, __half (*Ws)[APAD], int tid) {
#pragma unroll
    for (int rep = 0; rep < 4; rep++) {
        int w = tid + rep * 256;
        int n = w >> 4, kg = w & 15;
        *(uint4*)&Ws[n][kg * 8] = *(const uint4*)&Wt[n * H + kg * 8];
    }
}

// 64 rows x 128 cols, full k=128
__device__ __forceinline__ void hmma64(const __half (*As)[APAD], const __half (*Ws)[APAD],
                                       float (&acc)[2][4][4], int warp_m, int warp_n,
                                       int tm, int tk) {
#pragma unroll
    for (int msub = 0; msub < 2; msub++) {
        int mrow = msub * 32 + warp_m * 16 + tm;
#pragma unroll
        for (int kc = 0; kc < 8; kc++) {
            int k0 = kc * 16;
            unsigned a0 = *(const unsigned*)&As[mrow][k0 + tk];
            unsigned a1 = *(const unsigned*)&As[mrow + 8][k0 + tk];
            unsigned a2 = *(const unsigned*)&As[mrow][k0 + 8 + tk];
            unsigned a3 = *(const unsigned*)&As[mrow + 8][k0 + 8 + tk];
#pragma unroll
            for (int nt = 0; nt < 4; nt++) {
                int n0 = warp_n * 32 + nt * 8;
                unsigned b0 = *(const unsigned*)&Ws[n0 + tm][k0 + tk];
                unsigned b1 = *(const unsigned*)&Ws[n0 + tm][k0 + 8 + tk];
                hmma16816(acc[msub][nt][0], acc[msub][nt][1], acc[msub][nt][2], acc[msub][nt][3],
                          a0, a1, a2, a3, b0, b1);
            }
        }
    }
}

__device__ __forceinline__ void zero_acc(float (&acc)[2][4][4]) {
#pragma unroll
    for (int m = 0; m < 2; m++)
#pragma unroll
        for (int nt = 0; nt < 4; nt++)
#pragma unroll
            for (int i = 0; i < 4; i++) acc[m][nt][i] = 0.f;
}

// xf(fp16) = h(fp32) @ W  (layer 0)
__global__ void __launch_bounds__(256) gemm_xf(const float* __restrict__ A,
                                               const __half* __restrict__ Wt,
                                               __half* __restrict__ out, int M) {
    __shared__ __half As[64][APAD];
    __shared__ __half Ws[128][APAD];
    int tid = threadIdx.x;
    int warp = tid >> 5, lane = tid & 31;
    int warp_m = warp >> 2, warp_n = warp & 3;
    int tm = lane >> 2, tk = (lane & 3) * 2;
    int r0 = blockIdx.x * 64;
    stage_A64(A, As, r0, M, tid);
    stage_W(Wt, Ws, tid);
    __syncthreads();
    float acc[2][4][4];
    zero_acc(acc);
    hmma64(As, Ws, acc, warp_m, warp_n, tm, tk);
#pragma unroll
    for (int msub = 0; msub < 2; msub++) {
        int row1 = r0 + msub * 32 + warp_m * 16 + tm;
        int row2 = row1 + 8;
#pragma unroll
        for (int nt = 0; nt < 4; nt++) {
            int col = warp_n * 32 + nt * 8 + tk;
            if (row1 < M) *(__half2*)&out[(size_t)row1 * H + col] = __floats2half2_rn(acc[msub][nt][0], acc[msub][nt][1]);
            if (row2 < M) *(__half2*)&out[(size_t)row2 * H + col] = __floats2half2_rn(acc[msub][nt][2], acc[msub][nt][3]);
        }
    }
}

// h += ssp(aggh @ W2 + b2) @ W3 + b3;  then xf_next = h_new @ W1n
__global__ void __launch_bounds__(256) gemm_dualX(const __half* __restrict__ A,
                                                  const __half* __restrict__ W2t,
                                                  const float* __restrict__ b2,
                                                  const __half* __restrict__ W3t,
                                                  const float* __restrict__ b3,
                                                  float* __restrict__ hio,
                                                  const __half* __restrict__ W1n,
                                                  __half* __restrict__ xf, int M) {
    __shared__ __half As[64][APAD];
    __shared__ __half Ws[128][APAD];
    int tid = threadIdx.x;
    int warp = tid >> 5, lane = tid & 31;
    int warp_m = warp >> 2, warp_n = warp & 3;
    int tm = lane >> 2, tk = (lane & 3) * 2;
    int r0 = blockIdx.x * 64;

    stage_Ah64(A, As, r0, M, tid);
    stage_W(W2t, Ws, tid);
    __syncthreads();
    float acc[2][4][4];
    zero_acc(acc);
    hmma64(As, Ws, acc, warp_m, warp_n, tm, tk);
    __syncthreads();
    // epi 1: t = ssp(acc + b2) -> As ; Ws = W3t
#pragma unroll
    for (int msub = 0; msub < 2; msub++) {
        int lr1 = msub * 32 + warp_m * 16 + tm, lr2 = lr1 + 8;
#pragma unroll
        for (int nt = 0; nt < 4; nt++) {
            int col = warp_n * 32 + nt * 8 + tk;
            float2 bb = *(const float2*)&b2[col];
            *(__half2*)&As[lr1][col] = __floats2half2_rn(sspf(acc[msub][nt][0] + bb.x), sspf(acc[msub][nt][1] + bb.y));
            *(__half2*)&As[lr2][col] = __floats2half2_rn(sspf(acc[msub][nt][2] + bb.x), sspf(acc[msub][nt][3] + bb.y));
        }
    }
    stage_W(W3t, Ws, tid);
    __syncthreads();
    zero_acc(acc);
    hmma64(As, Ws, acc, warp_m, warp_n, tm, tk);
    __syncthreads();
    // epi 2: h_new = h_old + acc + b3 -> global fp32 AND As fp16
#pragma unroll
    for (int msub = 0; msub < 2; msub++) {
        int lr1 = msub * 32 + warp_m * 16 + tm, lr2 = lr1 + 8;
        int row1 = r0 + lr1, row2 = r0 + lr2;
#pragma unroll
        for (int nt = 0; nt < 4; nt++) {
            int col = warp_n * 32 + nt * 8 + tk;
            float2 bb = *(const float2*)&b3[col];
            float2 o1 = make_float2(0.f, 0.f), o2 = make_float2(0.f, 0.f);
            if (row1 < M) o1 = *(const float2*)&hio[(size_t)row1 * H + col];
            if (row2 < M) o2 = *(const float2*)&hio[(size_t)row2 * H + col];
            o1.x += acc[msub][nt][0] + bb.x; o1.y += acc[msub][nt][1] + bb.y;
            o2.x += acc[msub][nt][2] + bb.x; o2.y += acc[msub][nt][3] + bb.y;
            if (row1 < M) *(float2*)&hio[(size_t)row1 * H + col] = o1;
            if (row2 < M) *(float2*)&hio[(size_t)row2 * H + col] = o2;
            *(__half2*)&As[lr1][col] = __floats2half2_rn(o1.x, o1.y);
            *(__half2*)&As[lr2][col] = __floats2half2_rn(o2.x, o2.y);
        }
    }
    if (W1n) {
        stage_W(W1n, Ws, tid);
        __syncthreads();
        zero_acc(acc);
        hmma64(As, Ws, acc, warp_m, warp_n, tm, tk);
#pragma unroll
        for (int msub = 0; msub < 2; msub++) {
            int row1 = r0 + msub * 32 + warp_m * 16 + tm;
            int row2 = row1 + 8;
#pragma unroll
            for (int nt = 0; nt < 4; nt++) {
                int col = warp_n * 32 + nt * 8 + tk;
                if (row1 < M) *(__half2*)&xf[(size_t)row1 * H + col] = __floats2half2_rn(acc[msub][nt][0], acc[msub][nt][1]);
                if (row2 < M) *(__half2*)&xf[(size_t)row2 * H + col] = __floats2half2_rn(acc[msub][nt][2], acc[msub][nt][3]);
            }
        }
    }
}

// ======================= Edge gather (fp16 agg out) =======================
__global__ void edge_gather(const __half2* __restrict__ tab, int N) {
    int warp = (blockIdx.x * blockDim.x + threadIdx.x) >> 5;
    int lane = threadIdx.x & 31;
    if (warp >= N) return;
    int beg = g_rowptr[warp], end = g_rowptr[warp + 1];
    float a0 = 0.f, a1 = 0.f, a2 = 0.f, a3 = 0.f;
#pragma unroll 4
    for (int i = beg; i < end; i++) {
        int2 sd = g_csr[i];
        float d = __int_as_float(sd.y);
        float u = d * ((float)NBINS / CUTOFF_F);
        int i0 = min(max((int)u, 0), NBINS - 1);
        float fr = u - (float)i0;
        uint4 tp = *(const uint4*)&tab[(size_t)i0 * H + lane * 4];
        uint2 xq = *(const uint2*)&g_xfh[(size_t)sd.x * H + lane * 4];
        float2 p0 = __half22float2(*(__half2*)&tp.x);
        float2 p1 = __half22float2(*(__half2*)&tp.y);
        float2 p2 = __half22float2(*(__half2*)&tp.z);
        float2 p3 = __half22float2(*(__half2*)&tp.w);
        float2 xa = __half22float2(*(__half2*)&xq.x);
        float2 xb = __half22float2(*(__half2*)&xq.y);
        a0 += xa.x * fmaf(fr, p0.y - p0.x, p0.x);
        a1 += xa.y * fmaf(fr, p1.y - p1.x, p1.x);
        a2 += xb.x * fmaf(fr, p2.y - p2.x, p2.x);
        a3 += xb.y * fmaf(fr, p3.y - p3.x, p3.x);
    }
    __half2* op = (__half2*)&g_aggh[(size_t)warp * H + lane * 4];
    op[0] = __floats2half2_rn(a0, a1);
    op[1] = __floats2half2_rn(a2, a3);
}

// ======================= Readout: colsum of ssp(h @ o1w + b1) via HMMA ====
__global__ void __launch_bounds__(256) readout_h(const float* __restrict__ A,
                                                 const float* __restrict__ b1, int M) {
    __shared__ __half As[64][APAD];
    __shared__ __half Ws[64][APAD];
    __shared__ float scol[64];
    int tid = threadIdx.x;
    int warp = tid >> 5, lane = tid & 31;
    int warp_m = warp >> 2, warp_n = warp & 3;   // 2m x 4n, warp tile 16x16
    int tm = lane >> 2, tk = (lane & 3) * 2;
    int r0 = blockIdx.x * 64;
    if (tid < 64) scol[tid] = 0.f;
    stage_A64(A, As, r0, M, tid);
    stage_W64(g_o1t, Ws, tid);
    __syncthreads();
    float acc[2][2][4];
#pragma unroll
    for (int m = 0; m < 2; m++)
#pragma unroll
        for (int nt = 0; nt < 2; nt++)
#pragma unroll
            for (int i = 0; i < 4; i++) acc[m][nt][i] = 0.f;
#pragma unroll
    for (int msub = 0; msub < 2; msub++) {
        int mrow = msub * 32 + warp_m * 16 + tm;
#pragma unroll
        for (int kc = 0; kc < 8; kc++) {
            int k0 = kc * 16;
            unsigned a0 = *(const unsigned*)&As[mrow][k0 + tk];
            unsigned a1 = *(const unsigned*)&As[mrow + 8][k0 + tk];
            unsigned a2 = *(const unsigned*)&As[mrow][k0 + 8 + tk];
            unsigned a3 = *(const unsigned*)&As[mrow + 8][k0 + 8 + tk];
#pragma unroll
            for (int nt = 0; nt < 2; nt++) {
                int n0 = warp_n * 16 + nt * 8;
                unsigned b0 = *(const unsigned*)&Ws[n0 + tm][k0 + tk];
                unsigned bq1 = *(const unsigned*)&Ws[n0 + tm][k0 + 8 + tk];
                hmma16816(acc[msub][nt][0], acc[msub][nt][1], acc[msub][nt][2], acc[msub][nt][3],
                          a0, a1, a2, a3, b0, bq1);
            }
        }
    }
    // per-thread column partials with ssp + row guards
    float cs[2][2] = {{0.f, 0.f}, {0.f, 0.f}};
#pragma unroll
    for (int msub = 0; msub < 2; msub++) {
        int row1 = r0 + msub * 32 + warp_m * 16 + tm;
        int row2 = row1 + 8;
#pragma unroll
        for (int nt = 0; nt < 2; nt++) {
            int col = warp_n * 16 + nt * 8 + tk;
            float2 bb = *(const float2*)&b1[col];
            if (row1 < M) {
                cs[nt][0] += sspf(acc[msub][nt][0] + bb.x);
                cs[nt][1] += sspf(acc[msub][nt][1] + bb.y);
            }
            if (row2 < M) {
                cs[nt][0] += sspf(acc[msub][nt][2] + bb.x);
                cs[nt][1] += sspf(acc[msub][nt][3] + bb.y);
            }
        }
    }
    // reduce over tm (lanes stride 4)
#pragma unroll
    for (int off = 16; off >= 4; off >>= 1) {
#pragma unroll
        for (int nt = 0; nt < 2; nt++) {
            cs[nt][0] += __shfl_down_sync(0xffffffffu, cs[nt][0], off);
            cs[nt][1] += __shfl_down_sync(0xffffffffu, cs[nt][1], off);
        }
    }
    if (lane < 4) {
#pragma unroll
        for (int nt = 0; nt < 2; nt++) {
            int col = warp_n * 16 + nt * 8 + lane * 2;
            atomicAdd(&scol[col], cs[nt][0]);
            atomicAdd(&scol[col + 1], cs[nt][1]);
        }
    }
    __syncthreads();
    if (tid < 64) atomicAdd(&g_acc[tid], scol[tid]);
}

__global__ void readout_final(const float* __restrict__ o2w, const float* __restrict__ o2b,
                              const float* __restrict__ rw, const float* __restrict__ rb,
                              float* __restrict__ out, int N) {
    __shared__ float v[64];
    int t = threadIdx.x;
    float a = (float)N * o2b[t];
#pragma unroll 8
    for (int j = 0; j < 64; j++) a += g_acc[j] * o2w[j * 64 + t];
    v[t] = a;
    __syncthreads();
    if (t < 12) {
        float r = rb[t];
#pragma unroll
        for (int j = 0; j < 64; j++) r += v[j] * rw[j * 12 + t];
        out[t] = r;
    }
}

extern "C" void kernel_launch(void* const* d_in, const int* in_sizes, int n_in,
                              void* d_out, int out_size) {
    const int*   x    = (const int*)d_in[0];
    const int*   ei   = (const int*)d_in[1];
    const float* dist = (const float*)d_in[2];
    const float* emb  = (const float*)d_in[3];
    const float* mw1  = (const float*)d_in[4];
    const float* mb1  = (const float*)d_in[5];
    const float* mw2  = (const float*)d_in[6];
    const float* mb2  = (const float*)d_in[7];
    const float* l1w  = (const float*)d_in[8];
    const float* l2w  = (const float*)d_in[9];
    const float* l2b  = (const float*)d_in[10];
    const float* lw   = (const float*)d_in[11];
    const float* lb   = (const float*)d_in[12];
    const float* o1w  = (const float*)d_in[13];
    const float* o1b  = (const float*)d_in[14];
    const float* o2w  = (const float*)d_in[15];
    const float* o2b  = (const float*)d_in[16];
    const float* rw   = (const float*)d_in[17];
    const float* rb   = (const float*)d_in[18];

    int N = in_sizes[0];
    int E = in_sizes[2];
    int L = in_sizes[4] / (G * H);

    float *pacc;
    int *prow;
    cudaGetSymbolAddress((void**)&pacc, g_acc);
    cudaGetSymbolAddress((void**)&prow, g_rowptr);
    float *ph;
    __half *pxfh, *paggh, *pw1t, *pw2t, *pw3t;
    __half2 *ptab;
    cudaGetSymbolAddress((void**)&ph, g_h);
    cudaGetSymbolAddress((void**)&pxfh, g_xfh);
    cudaGetSymbolAddress((void**)&paggh, g_aggh);
    cudaGetSymbolAddress((void**)&pw1t, g_w1t);
    cudaGetSymbolAddress((void**)&pw2t, g_w2t);
    cudaGetSymbolAddress((void**)&pw3t, g_w3t);
    cudaGetSymbolAddress((void**)&ptab, g_tab2);

    const int* esrc = ei;
    const int* edst = ei + E;

    int nb64 = (N + 63) / 64;
    int nbE = (N + 7) / 8;

    embed_kernel<<<N, 128>>>(x, emb, N);                                  // k1
    cudaMemsetAsync(prow, 0, (N + 1) * sizeof(int));
    hist_kernel<<<(E + 255) / 256, 256>>>(edst, E);                       // k2
    scan_kernel<<<1, 1024>>>(N + 1);                                      // k3
    scatter_kernel<<<(E + 255) / 256, 256>>>(esrc, edst, dist, E);        // k4 <- profiled
    convert_weights<<<256, 256>>>(l1w, l2w, lw, o1w, L);                  // k5
    gemm_xf<<<nb64, 256>>>(ph, pw1t, pxfh, N);                            // k6
    dim3 tgrid(NBINS / 2, L);
    table_all<<<tgrid, 128>>>(mw1, mb1, mw2, mb2);                        // k7

    for (int l = 0; l < L; l++) {
        edge_gather<<<nbE, 256>>>(ptab + (size_t)l * NBINS * H, N);
        const __half* w1n = (l + 1 < L) ? pw1t + (size_t)(l + 1) * H * H : nullptr;
        gemm_dualX<<<nb64, 256>>>(paggh, pw2t + (size_t)l * H * H, l2b + (size_t)l * H,
                                  pw3t + (size_t)l * H * H, lb + (size_t)l * H,
                                  ph, w1n, pxfh, N);
    }

    cudaMemsetAsync(pacc, 0, 64 * sizeof(float));
    readout_h<<<nb64, 256>>>(ph, o1b, N);
    readout_final<<<1, 64>>>(o2w, o2b, rw, rb, (float*)d_out, N);
}